// round 1
// baseline (speedup 1.0000x reference)
#include <cuda_runtime.h>
#include <cuda_bf16.h>

// Problem constants (fixed by the dataset)
#define NN 50000
#define EE 800000
#define ETOT 850000   // EE + NN self-loops
#define HH 4
#define CC 32
#define HC 128        // HH*CC, also input dim of every layer

// ---------------- scratch (device globals: allocation-free) ----------------
__device__ float g_lin[NN * HC];    // linear output of current layer (messages)
__device__ float g_tmp[NN * HC];    // aggregation accumulator
__device__ float g_act[NN * HC];    // activated layer output (next layer input)
__device__ float g_h3[NN * CC];     // layer-3 output (link embedding)
__device__ float g_alsrc[NN * HH];
__device__ float g_aldst[NN * HH];
__device__ float g_emax[NN * HH];
__device__ float g_denom[NN * HH];
__device__ float g_w[ETOT * HH];    // per-edge logits -> exp weights
__device__ int   g_src[ETOT];
__device__ int   g_dst[ETOT];
__device__ int   g_is64;

// ---------------- helpers ----------------
__device__ __forceinline__ void atomicMaxF(float* addr, float v) {
    // monotonic-bits trick: nonneg -> signed int max, neg -> unsigned min
    if (v >= 0.f) atomicMax((int*)addr, __float_as_int(v));
    else          atomicMin((unsigned int*)addr, __float_as_uint(v));
}

// ---------------- edge prep ----------------
__global__ void detect_kernel(const int* __restrict__ buf) {
    if (blockIdx.x == 0 && threadIdx.x == 0) {
        int orv = 0;
        #pragma unroll
        for (int i = 1; i < 64; i += 2) orv |= buf[i];
        g_is64 = (orv == 0) ? 1 : 0;   // int64 little-endian -> high words zero
    }
}

__global__ void prep_kernel(const int* __restrict__ buf) {
    int t = blockIdx.x * blockDim.x + threadIdx.x;
    if (t >= ETOT) return;
    int is64 = g_is64;
    if (t < EE) {
        if (is64) {
            g_src[t] = buf[2 * t];
            g_dst[t] = buf[2 * (EE + t)];
        } else {
            g_src[t] = buf[t];
            g_dst[t] = buf[EE + t];
        }
    } else {
        int v = t - EE;
        g_src[t] = v;
        g_dst[t] = v;
    }
}

// ---------------- GEMM: Y = X @ W, X is [NN,128], W is [128,OUT] ----------------
template<int OUT, bool FROMACT>
__global__ void gemm_kernel(const float* __restrict__ X, const float* __restrict__ W) {
    constexpr int ROWS = 16;
    constexpr int G = 128 / OUT;     // row groups per block
    constexpr int RPT = ROWS / G;    // rows per thread
    __shared__ float xs[ROWS][HC + 1];

    const float* __restrict__ Xp = FROMACT ? g_act : X;
    int tid = threadIdx.x;
    int row0 = blockIdx.x * ROWS;

    for (int i = tid; i < ROWS * HC; i += 128) {
        int r = i >> 7, c = i & 127;
        xs[r][c] = Xp[(row0 + r) * HC + c];
    }
    __syncthreads();

    int col = tid % OUT;
    int rg  = tid / OUT;
    float acc[RPT];
    #pragma unroll
    for (int j = 0; j < RPT; j++) acc[j] = 0.f;

    #pragma unroll 4
    for (int k = 0; k < HC; k++) {
        float w = __ldg(&W[k * OUT + col]);
        #pragma unroll
        for (int j = 0; j < RPT; j++)
            acc[j] += xs[rg + j * G][k] * w;
    }
    #pragma unroll
    for (int j = 0; j < RPT; j++)
        g_lin[(row0 + rg + j * G) * OUT + col] = acc[j];
}

// ---------------- per-node attention logits ----------------
template<int H_>
__global__ void al_kernel(const float* __restrict__ a_src, const float* __restrict__ a_dst) {
    int t = blockIdx.x * blockDim.x + threadIdx.x;
    if (t >= NN * H_) return;
    int node = t / H_, hh = t % H_;
    const float* hp = g_lin + (node * H_ + hh) * CC;
    float ss = 0.f, sd = 0.f;
    #pragma unroll
    for (int c = 0; c < CC; c++) {
        float v = hp[c];
        ss += v * a_src[hh * CC + c];
        sd += v * a_dst[hh * CC + c];
    }
    g_alsrc[t] = ss;
    g_aldst[t] = sd;
}

// ---------------- init accumulators ----------------
template<int H_>
__global__ void init_kernel() {
    int t = blockIdx.x * blockDim.x + threadIdx.x;
    if (t < NN * H_ * CC) g_tmp[t] = 0.f;
    if (t < NN * H_) { g_emax[t] = -3.0e38f; g_denom[t] = 0.f; }
}

// ---------------- edge pass A: leaky-relu logits + segment max ----------------
template<int H_>
__global__ void edge_max_kernel() {
    int e = blockIdx.x * blockDim.x + threadIdx.x;
    if (e >= ETOT) return;
    int s = g_src[e], d = g_dst[e];
    #pragma unroll
    for (int hh = 0; hh < H_; hh++) {
        float v = g_alsrc[s * H_ + hh] + g_aldst[d * H_ + hh];
        v = (v > 0.f) ? v : 0.2f * v;
        g_w[e * H_ + hh] = v;
        atomicMaxF(&g_emax[d * H_ + hh], v);
    }
}

// ---------------- edge pass B: exp + segment sum ----------------
template<int H_>
__global__ void edge_sum_kernel() {
    int e = blockIdx.x * blockDim.x + threadIdx.x;
    if (e >= ETOT) return;
    int d = g_dst[e];
    if (H_ == 4) {
        float4 w = *(const float4*)&g_w[e * 4];
        float4 m = *(const float4*)&g_emax[d * 4];
        w.x = __expf(w.x - m.x);
        w.y = __expf(w.y - m.y);
        w.z = __expf(w.z - m.z);
        w.w = __expf(w.w - m.w);
        *(float4*)&g_w[e * 4] = w;
        atomicAdd((float4*)&g_denom[d * 4], w);
    } else {
        float w = __expf(g_w[e] - g_emax[d]);
        g_w[e] = w;
        atomicAdd(&g_denom[d], w);
    }
}

// ---------------- edge pass C: weighted message scatter ----------------
template<int H_>
__global__ void edge_scatter_kernel() {
    int t = blockIdx.x * blockDim.x + threadIdx.x;
    if (t >= ETOT * H_) return;
    int e = t / H_;
    int hh = t - e * H_;
    int s = g_src[e], d = g_dst[e];
    float alpha = g_w[t] / (g_denom[d * H_ + hh] + 1e-16f);
    const float4* hs = (const float4*)(g_lin + (s * H_ + hh) * CC);
    float4* o = (float4*)(g_tmp + (d * H_ + hh) * CC);
    #pragma unroll
    for (int i = 0; i < 8; i++) {
        float4 v = hs[i];
        v.x *= alpha; v.y *= alpha; v.z *= alpha; v.w *= alpha;
        atomicAdd(o + i, v);
    }
}

// ---------------- finalize: bias + ELU ----------------
__global__ void finalize12_kernel(const float* __restrict__ b) {
    int t = blockIdx.x * blockDim.x + threadIdx.x;
    if (t >= NN * HC) return;
    float v = g_tmp[t] + b[t & (HC - 1)];
    g_act[t] = (v > 0.f) ? v : (__expf(v) - 1.f);
}

__global__ void finalize3_kernel(const float* __restrict__ b) {
    int t = blockIdx.x * blockDim.x + threadIdx.x;
    if (t >= NN * CC) return;
    g_h3[t] = g_tmp[t] + b[t & (CC - 1)];
}

// ---------------- output head ----------------
__global__ void head_kernel(const float* __restrict__ Wc, const float* __restrict__ bc,
                            float* __restrict__ out) {
    int n = blockIdx.x * blockDim.x + threadIdx.x;
    if (n >= NN) return;
    const float* h = g_h3 + n * CC;
    float o0 = bc[0], o1 = bc[1];
    #pragma unroll
    for (int c = 0; c < CC; c++) {
        float v = h[c];
        o0 += v * Wc[c * 2 + 0];
        o1 += v * Wc[c * 2 + 1];
    }
    out[n * 2 + 0] = o0;
    out[n * 2 + 1] = o1;
    float* dst = out + NN * 2 + n * CC;
    #pragma unroll
    for (int c = 0; c < CC; c++) dst[c] = h[c];
}

// ---------------- launch ----------------
extern "C" void kernel_launch(void* const* d_in, const int* in_sizes, int n_in,
                              void* d_out, int out_size) {
    const float* x   = (const float*)d_in[0];
    const int*   ei  = (const int*)d_in[1];   // int32 or int64, auto-detected
    const float* W1  = (const float*)d_in[2];
    const float* a1s = (const float*)d_in[3];
    const float* a1d = (const float*)d_in[4];
    const float* b1  = (const float*)d_in[5];
    const float* W2  = (const float*)d_in[6];
    const float* a2s = (const float*)d_in[7];
    const float* a2d = (const float*)d_in[8];
    const float* b2  = (const float*)d_in[9];
    const float* W3  = (const float*)d_in[10];
    const float* a3s = (const float*)d_in[11];
    const float* a3d = (const float*)d_in[12];
    const float* b3  = (const float*)d_in[13];
    const float* Wc  = (const float*)d_in[14];
    const float* bc  = (const float*)d_in[15];
    float* out = (float*)d_out;

    const int T = 256;
    const int gE   = (ETOT + T - 1) / T;
    const int gE4  = (ETOT * 4 + T - 1) / T;
    const int gNH  = (NN * HH + T - 1) / T;
    const int gN1  = (NN + T - 1) / T;
    const int gFull = (NN * HC + T - 1) / T;
    const int gC32 = (NN * CC + T - 1) / T;

    detect_kernel<<<1, 32>>>(ei);
    prep_kernel<<<gE, T>>>(ei);

    // ---- layer 1 ----
    gemm_kernel<128, false><<<NN / 16, 128>>>(x, W1);
    al_kernel<4><<<gNH, T>>>(a1s, a1d);
    init_kernel<4><<<gFull, T>>>();
    edge_max_kernel<4><<<gE, T>>>();
    edge_sum_kernel<4><<<gE, T>>>();
    edge_scatter_kernel<4><<<gE4, T>>>();
    finalize12_kernel<<<gFull, T>>>(b1);

    // ---- layer 2 ----
    gemm_kernel<128, true><<<NN / 16, 128>>>(nullptr, W2);
    al_kernel<4><<<gNH, T>>>(a2s, a2d);
    init_kernel<4><<<gFull, T>>>();
    edge_max_kernel<4><<<gE, T>>>();
    edge_sum_kernel<4><<<gE, T>>>();
    edge_scatter_kernel<4><<<gE4, T>>>();
    finalize12_kernel<<<gFull, T>>>(b2);

    // ---- layer 3 (heads=1, no concat/activation) ----
    gemm_kernel<32, true><<<NN / 16, 128>>>(nullptr, W3);
    al_kernel<1><<<gN1, T>>>(a3s, a3d);
    init_kernel<1><<<gC32, T>>>();
    edge_max_kernel<1><<<gE, T>>>();
    edge_sum_kernel<1><<<gE, T>>>();
    edge_scatter_kernel<1><<<gE, T>>>();
    finalize3_kernel<<<gC32, T>>>(b3);

    // ---- classifier head + link embedding copy ----
    head_kernel<<<gN1, T>>>(Wc, bc, out);
}

// round 2
// speedup vs baseline: 1.8732x; 1.8732x over previous
#include <cuda_runtime.h>
#include <cuda_bf16.h>

// Problem constants (fixed by the dataset)
#define NN 50000
#define EE 800000
#define ETOT 850000   // EE + NN self-loops
#define HH 4
#define CC 32
#define HC 128        // HH*CC

// ---------------- scratch (device globals: allocation-free) ----------------
__device__ float g_lin[NN * HC];     // linear output of current layer (messages)
__device__ float g_act[NN * HC];     // activated layer output (next layer input)
__device__ float g_h3[NN * CC];      // layer-3 output (link embedding)
__device__ float g_alsrc[NN * HH];
__device__ float g_aldst[NN * HH];
__device__ float g_w[ETOT * HH];     // per-CSR-slot logits -> exp weights
__device__ int   g_src[ETOT];
__device__ int   g_dst[ETOT];
__device__ int   g_csrc[ETOT];       // CSR: src node per slot, grouped by dst
__device__ int   g_rowptr[NN + 1];
__device__ int   g_fill[NN];
__device__ int   g_is64;

// ---------------- edge prep ----------------
__global__ void detect_kernel(const int* __restrict__ buf) {
    if (blockIdx.x == 0 && threadIdx.x == 0) {
        int orv = 0;
        #pragma unroll
        for (int i = 1; i < 64; i += 2) orv |= buf[i];
        g_is64 = (orv == 0) ? 1 : 0;   // int64 little-endian -> high words zero
    }
}

__global__ void prep_kernel(const int* __restrict__ buf) {
    int t = blockIdx.x * blockDim.x + threadIdx.x;
    if (t >= ETOT) return;
    int is64 = g_is64;
    if (t < EE) {
        if (is64) {
            g_src[t] = buf[2 * t];
            g_dst[t] = buf[2 * (EE + t)];
        } else {
            g_src[t] = buf[t];
            g_dst[t] = buf[EE + t];
        }
    } else {
        int v = t - EE;
        g_src[t] = v;
        g_dst[t] = v;
    }
}

__global__ void zero_fill_kernel() {
    int t = blockIdx.x * blockDim.x + threadIdx.x;
    if (t < NN) g_fill[t] = 0;
}

__global__ void count_kernel() {
    int t = blockIdx.x * blockDim.x + threadIdx.x;
    if (t < ETOT) atomicAdd(&g_fill[g_dst[t]], 1);
}

// single-block exclusive scan of g_fill[0..NN) -> g_rowptr
__global__ void scan_kernel() {
    __shared__ int sm[1024];
    __shared__ int run;
    int tid = threadIdx.x;
    if (tid == 0) run = 0;
    __syncthreads();
    for (int base = 0; base < NN; base += 1024) {
        int idx = base + tid;
        int v = (idx < NN) ? g_fill[idx] : 0;
        sm[tid] = v;
        __syncthreads();
        int base_run = run;
        // Hillis-Steele inclusive scan
        for (int o = 1; o < 1024; o <<= 1) {
            int t2 = (tid >= o) ? sm[tid - o] : 0;
            __syncthreads();
            sm[tid] += t2;
            __syncthreads();
        }
        if (idx < NN) g_rowptr[idx] = base_run + sm[tid] - v;
        __syncthreads();
        if (tid == 0) run = base_run + sm[1023];
        __syncthreads();
    }
    if (tid == 0) g_rowptr[NN] = ETOT;
}

__global__ void csr_fill_kernel() {
    int t = blockIdx.x * blockDim.x + threadIdx.x;
    if (t >= ETOT) return;
    int d = g_dst[t];
    int pos = g_rowptr[d] + atomicAdd(&g_fill[d], 1);
    g_csrc[pos] = g_src[t];
}

// ---------------- GEMM: Y = X @ W, X is [NN,128], W is [128,OUT] ----------------
template<int OUT, bool FROMACT>
__global__ void gemm_kernel(const float* __restrict__ X, const float* __restrict__ W) {
    constexpr int ROWS = 16;
    constexpr int G = 128 / OUT;     // row groups per block
    constexpr int RPT = ROWS / G;    // rows per thread
    __shared__ float xs[ROWS][HC + 1];

    const float* __restrict__ Xp = FROMACT ? g_act : X;
    int tid = threadIdx.x;
    int row0 = blockIdx.x * ROWS;

    for (int i = tid; i < ROWS * HC; i += 128) {
        int r = i >> 7, c = i & 127;
        xs[r][c] = Xp[(row0 + r) * HC + c];
    }
    __syncthreads();

    int col = tid % OUT;
    int rg  = tid / OUT;
    float acc[RPT];
    #pragma unroll
    for (int j = 0; j < RPT; j++) acc[j] = 0.f;

    #pragma unroll 4
    for (int k = 0; k < HC; k++) {
        float w = __ldg(&W[k * OUT + col]);
        #pragma unroll
        for (int j = 0; j < RPT; j++)
            acc[j] += xs[rg + j * G][k] * w;
    }
    #pragma unroll
    for (int j = 0; j < RPT; j++)
        g_lin[(row0 + rg + j * G) * OUT + col] = acc[j];
}

// ---------------- per-node attention logits (warp per node, coalesced) -------
__global__ void al4_kernel(const float* __restrict__ a_src, const float* __restrict__ a_dst) {
    int warp = (blockIdx.x * blockDim.x + threadIdx.x) >> 5;
    if (warp >= NN) return;
    int lane = threadIdx.x & 31;
    // lane covers columns [lane*4, lane*4+4) -> head = lane/8
    float4 v  = ((const float4*)(g_lin + warp * HC))[lane];
    float4 as = ((const float4*)a_src)[lane];
    float4 ad = ((const float4*)a_dst)[lane];
    float ss = v.x * as.x + v.y * as.y + v.z * as.z + v.w * as.w;
    float sd = v.x * ad.x + v.y * ad.y + v.z * ad.z + v.w * ad.w;
    #pragma unroll
    for (int o = 4; o >= 1; o >>= 1) {
        ss += __shfl_xor_sync(0xffffffff, ss, o);
        sd += __shfl_xor_sync(0xffffffff, sd, o);
    }
    if ((lane & 7) == 0) {
        int h = lane >> 3;
        g_alsrc[warp * HH + h] = ss;
        g_aldst[warp * HH + h] = sd;
    }
}

__global__ void al1_kernel(const float* __restrict__ a_src, const float* __restrict__ a_dst) {
    int warp = (blockIdx.x * blockDim.x + threadIdx.x) >> 5;
    if (warp >= NN) return;
    int lane = threadIdx.x & 31;
    float v = g_lin[warp * CC + lane];
    float ss = v * a_src[lane];
    float sd = v * a_dst[lane];
    #pragma unroll
    for (int o = 16; o >= 1; o >>= 1) {
        ss += __shfl_xor_sync(0xffffffff, ss, o);
        sd += __shfl_xor_sync(0xffffffff, sd, o);
    }
    if (lane == 0) {
        g_alsrc[warp] = ss;
        g_aldst[warp] = sd;
    }
}

// ---------------- fused GAT aggregation: warp per destination node ----------
// H=4: max -> exp/sum -> weighted gather -> bias (+ELU)
__global__ void gat_agg4_kernel(const float* __restrict__ b, int do_elu) {
    int warp = (blockIdx.x * blockDim.x + threadIdx.x) >> 5;
    if (warp >= NN) return;
    int lane = threadIdx.x & 31;
    int d = warp;
    int start = g_rowptr[d], end = g_rowptr[d + 1];

    float4 ad = *(const float4*)&g_aldst[d * HH];

    // pass 1: leaky-relu logits + per-head max
    float4 m = make_float4(-3.0e38f, -3.0e38f, -3.0e38f, -3.0e38f);
    for (int i = start + lane; i < end; i += 32) {
        int s = g_csrc[i];
        float4 v = *(const float4*)&g_alsrc[s * HH];
        v.x += ad.x; v.y += ad.y; v.z += ad.z; v.w += ad.w;
        v.x = (v.x > 0.f) ? v.x : 0.2f * v.x;
        v.y = (v.y > 0.f) ? v.y : 0.2f * v.y;
        v.z = (v.z > 0.f) ? v.z : 0.2f * v.z;
        v.w = (v.w > 0.f) ? v.w : 0.2f * v.w;
        *(float4*)&g_w[i * HH] = v;
        m.x = fmaxf(m.x, v.x); m.y = fmaxf(m.y, v.y);
        m.z = fmaxf(m.z, v.z); m.w = fmaxf(m.w, v.w);
    }
    #pragma unroll
    for (int o = 16; o >= 1; o >>= 1) {
        m.x = fmaxf(m.x, __shfl_xor_sync(0xffffffff, m.x, o));
        m.y = fmaxf(m.y, __shfl_xor_sync(0xffffffff, m.y, o));
        m.z = fmaxf(m.z, __shfl_xor_sync(0xffffffff, m.z, o));
        m.w = fmaxf(m.w, __shfl_xor_sync(0xffffffff, m.w, o));
    }

    // pass 2: exp + per-head sum
    float4 ssum = make_float4(0.f, 0.f, 0.f, 0.f);
    for (int i = start + lane; i < end; i += 32) {
        float4 w = *(const float4*)&g_w[i * HH];
        w.x = __expf(w.x - m.x); w.y = __expf(w.y - m.y);
        w.z = __expf(w.z - m.z); w.w = __expf(w.w - m.w);
        *(float4*)&g_w[i * HH] = w;
        ssum.x += w.x; ssum.y += w.y; ssum.z += w.z; ssum.w += w.w;
    }
    #pragma unroll
    for (int o = 16; o >= 1; o >>= 1) {
        ssum.x += __shfl_xor_sync(0xffffffff, ssum.x, o);
        ssum.y += __shfl_xor_sync(0xffffffff, ssum.y, o);
        ssum.z += __shfl_xor_sync(0xffffffff, ssum.z, o);
        ssum.w += __shfl_xor_sync(0xffffffff, ssum.w, o);
    }
    float4 rd;
    rd.x = 1.f / (ssum.x + 1e-16f);
    rd.y = 1.f / (ssum.y + 1e-16f);
    rd.z = 1.f / (ssum.z + 1e-16f);
    rd.w = 1.f / (ssum.w + 1e-16f);

    // pass 3: weighted gather (lane = channel within each head)
    float a0 = 0.f, a1 = 0.f, a2 = 0.f, a3 = 0.f;
    for (int i = start; i < end; i++) {
        int s = g_csrc[i];                           // broadcast
        float4 w = *(const float4*)&g_w[i * HH];     // broadcast
        const float* hp = g_lin + s * HC;
        a0 += w.x * hp[lane];                        // 128B coalesced
        a1 += w.y * hp[32 + lane];
        a2 += w.z * hp[64 + lane];
        a3 += w.w * hp[96 + lane];
    }
    a0 = a0 * rd.x + b[lane];
    a1 = a1 * rd.y + b[32 + lane];
    a2 = a2 * rd.z + b[64 + lane];
    a3 = a3 * rd.w + b[96 + lane];
    if (do_elu) {
        a0 = (a0 > 0.f) ? a0 : (__expf(a0) - 1.f);
        a1 = (a1 > 0.f) ? a1 : (__expf(a1) - 1.f);
        a2 = (a2 > 0.f) ? a2 : (__expf(a2) - 1.f);
        a3 = (a3 > 0.f) ? a3 : (__expf(a3) - 1.f);
    }
    float* o = g_act + d * HC;
    o[lane] = a0; o[32 + lane] = a1; o[64 + lane] = a2; o[96 + lane] = a3;
}

// H=1 version -> writes g_h3 (bias, no activation)
__global__ void gat_agg1_kernel(const float* __restrict__ b) {
    int warp = (blockIdx.x * blockDim.x + threadIdx.x) >> 5;
    if (warp >= NN) return;
    int lane = threadIdx.x & 31;
    int d = warp;
    int start = g_rowptr[d], end = g_rowptr[d + 1];

    float ad = g_aldst[d];
    float m = -3.0e38f;
    for (int i = start + lane; i < end; i += 32) {
        int s = g_csrc[i];
        float v = g_alsrc[s] + ad;
        v = (v > 0.f) ? v : 0.2f * v;
        g_w[i] = v;
        m = fmaxf(m, v);
    }
    #pragma unroll
    for (int o = 16; o >= 1; o >>= 1)
        m = fmaxf(m, __shfl_xor_sync(0xffffffff, m, o));

    float ssum = 0.f;
    for (int i = start + lane; i < end; i += 32) {
        float w = __expf(g_w[i] - m);
        g_w[i] = w;
        ssum += w;
    }
    #pragma unroll
    for (int o = 16; o >= 1; o >>= 1)
        ssum += __shfl_xor_sync(0xffffffff, ssum, o);
    float rd = 1.f / (ssum + 1e-16f);

    float acc = 0.f;
    for (int i = start; i < end; i++) {
        int s = g_csrc[i];
        float w = g_w[i];
        acc += w * g_lin[s * CC + lane];
    }
    g_h3[d * CC + lane] = acc * rd + b[lane];
}

// ---------------- output head ----------------
__global__ void head_kernel(const float* __restrict__ Wc, const float* __restrict__ bc,
                            float* __restrict__ out) {
    int n = blockIdx.x * blockDim.x + threadIdx.x;
    if (n >= NN) return;
    const float* h = g_h3 + n * CC;
    float o0 = bc[0], o1 = bc[1];
    #pragma unroll
    for (int c = 0; c < CC; c++) {
        float v = h[c];
        o0 += v * Wc[c * 2 + 0];
        o1 += v * Wc[c * 2 + 1];
    }
    out[n * 2 + 0] = o0;
    out[n * 2 + 1] = o1;
    float* dst = out + NN * 2 + n * CC;
    #pragma unroll
    for (int c = 0; c < CC; c++) dst[c] = h[c];
}

// ---------------- launch ----------------
extern "C" void kernel_launch(void* const* d_in, const int* in_sizes, int n_in,
                              void* d_out, int out_size) {
    const float* x   = (const float*)d_in[0];
    const int*   ei  = (const int*)d_in[1];   // int32 or int64, auto-detected
    const float* W1  = (const float*)d_in[2];
    const float* a1s = (const float*)d_in[3];
    const float* a1d = (const float*)d_in[4];
    const float* b1  = (const float*)d_in[5];
    const float* W2  = (const float*)d_in[6];
    const float* a2s = (const float*)d_in[7];
    const float* a2d = (const float*)d_in[8];
    const float* b2  = (const float*)d_in[9];
    const float* W3  = (const float*)d_in[10];
    const float* a3s = (const float*)d_in[11];
    const float* a3d = (const float*)d_in[12];
    const float* b3  = (const float*)d_in[13];
    const float* Wc  = (const float*)d_in[14];
    const float* bc  = (const float*)d_in[15];
    float* out = (float*)d_out;

    const int T = 256;
    const int gE  = (ETOT + T - 1) / T;
    const int gN  = (NN + T - 1) / T;
    const int gW  = (NN * 32 + T - 1) / T;   // warp-per-node grids

    // ---- CSR build (once per launch) ----
    detect_kernel<<<1, 32>>>(ei);
    prep_kernel<<<gE, T>>>(ei);
    zero_fill_kernel<<<gN, T>>>();
    count_kernel<<<gE, T>>>();
    scan_kernel<<<1, 1024>>>();
    zero_fill_kernel<<<gN, T>>>();
    csr_fill_kernel<<<gE, T>>>();

    // ---- layer 1 ----
    gemm_kernel<128, false><<<NN / 16, 128>>>(x, W1);
    al4_kernel<<<gW, T>>>(a1s, a1d);
    gat_agg4_kernel<<<gW, T>>>(b1, 1);

    // ---- layer 2 ----
    gemm_kernel<128, true><<<NN / 16, 128>>>(nullptr, W2);
    al4_kernel<<<gW, T>>>(a2s, a2d);
    gat_agg4_kernel<<<gW, T>>>(b2, 1);

    // ---- layer 3 (heads=1, no concat/activation) ----
    gemm_kernel<32, true><<<NN / 16, 128>>>(nullptr, W3);
    al1_kernel<<<gW, T>>>(a3s, a3d);
    gat_agg1_kernel<<<gW, T>>>(b3);

    // ---- classifier head + link embedding copy ----
    head_kernel<<<gN, T>>>(Wc, bc, out);
}

// round 3
// speedup vs baseline: 2.7158x; 1.4498x over previous
#include <cuda_runtime.h>
#include <cuda_bf16.h>

// Problem constants (fixed by the dataset)
#define NN 50000
#define EE 800000
#define ETOT 850000   // EE + NN self-loops
#define HH 4
#define CC 32
#define HC 128        // HH*CC

// ---------------- scratch (device globals: allocation-free) ----------------
__device__ float g_lin[NN * HC];     // linear output of current layer (messages)
__device__ float g_act[NN * HC];     // activated layer output (next layer input)
__device__ float g_h3[NN * CC];      // layer-3 output (link embedding)
__device__ float g_alsrc[NN * HH];
__device__ float g_aldst[NN * HH];
__device__ float g_w[ETOT * HH];     // per-CSR-slot logits -> exp weights
__device__ int   g_src[ETOT];
__device__ int   g_dst[ETOT];
__device__ int   g_csrc[ETOT];       // CSR: src node per slot, grouped by dst
__device__ int   g_rowptr[NN + 1];
__device__ int   g_fill[NN];
__device__ int   g_is64;

// ---------------- edge prep ----------------
__global__ void detect_kernel(const int* __restrict__ buf) {
    if (blockIdx.x == 0 && threadIdx.x == 0) {
        int orv = 0;
        #pragma unroll
        for (int i = 1; i < 64; i += 2) orv |= buf[i];
        g_is64 = (orv == 0) ? 1 : 0;   // int64 little-endian -> high words zero
    }
}

__global__ void zero_fill_kernel() {
    int t = blockIdx.x * blockDim.x + threadIdx.x;
    if (t < NN) g_fill[t] = 0;
}

// decode edges + degree count in one pass
__global__ void prep_count_kernel(const int* __restrict__ buf) {
    int t = blockIdx.x * blockDim.x + threadIdx.x;
    if (t >= ETOT) return;
    int s, d;
    if (t < EE) {
        if (g_is64) {
            s = buf[2 * t];
            d = buf[2 * (EE + t)];
        } else {
            s = buf[t];
            d = buf[EE + t];
        }
    } else {
        s = d = t - EE;
    }
    g_src[t] = s;
    g_dst[t] = d;
    atomicAdd(&g_fill[d], 1);
}

// single-block segmented scan: g_fill (counts) -> g_rowptr (exclusive prefix),
// and re-seed g_fill with the row start pointer for csr_fill's slot allocator.
__global__ void scan_kernel() {
    __shared__ int wsum[32];
    const int tid = threadIdx.x;
    const int IPT = 49;               // 1024*49 >= NN
    int base = tid * IPT;
    int s = 0;
    for (int i = 0; i < IPT; i++) {
        int idx = base + i;
        if (idx < NN) s += g_fill[idx];
    }
    int lane = tid & 31, wid = tid >> 5;
    int v = s;
    #pragma unroll
    for (int o = 1; o < 32; o <<= 1) {
        int t2 = __shfl_up_sync(0xffffffff, v, o);
        if (lane >= o) v += t2;
    }
    if (lane == 31) wsum[wid] = v;
    __syncthreads();
    if (wid == 0) {
        int w = wsum[lane];
        #pragma unroll
        for (int o = 1; o < 32; o <<= 1) {
            int t2 = __shfl_up_sync(0xffffffff, w, o);
            if (lane >= o) w += t2;
        }
        wsum[lane] = w;
    }
    __syncthreads();
    int run = v - s + (wid > 0 ? wsum[wid - 1] : 0);   // exclusive prefix of this segment
    for (int i = 0; i < IPT; i++) {
        int idx = base + i;
        if (idx < NN) {
            int c = g_fill[idx];
            g_rowptr[idx] = run;
            g_fill[idx] = run;
            run += c;
        }
    }
    if (tid == 0) g_rowptr[NN] = ETOT;
}

__global__ void csr_fill_kernel() {
    int t = blockIdx.x * blockDim.x + threadIdx.x;
    if (t >= ETOT) return;
    int pos = atomicAdd(&g_fill[g_dst[t]], 1);
    g_csrc[pos] = g_src[t];
}

// ---------------- register-blocked GEMM: Y = X @ W ----------------
// X [NN,128], W [128,OUT]. Thread computes 8 nodes x CPT cols.
template<int OUT, bool FROMACT>
__global__ __launch_bounds__(128) void gemm_kernel(const float* __restrict__ X,
                                                   const float* __restrict__ W) {
    constexpr int NPB = (OUT == 128) ? 64 : 128;   // nodes per block
    constexpr int CPT = (OUT == 128) ? 8 : 4;      // cols per thread
    constexpr int KC  = 32;                        // k chunk
    constexpr int CGN = OUT / CPT;                 // col groups (16 or 8)

    __shared__ float Xs[KC][NPB];
    __shared__ float Ws[KC][OUT];

    const float* __restrict__ Xp = FROMACT ? g_act : X;
    const int tid = threadIdx.x;
    const int cg = tid % CGN;
    const int ng = tid / CGN;
    const int row0 = blockIdx.x * NPB;

    float acc[8][CPT];
    #pragma unroll
    for (int i = 0; i < 8; i++)
        #pragma unroll
        for (int j = 0; j < CPT; j++) acc[i][j] = 0.f;

    for (int kc = 0; kc < HC; kc += KC) {
        __syncthreads();
        // stage X chunk transposed: Xs[k][node]
        #pragma unroll
        for (int e = tid; e < KC * NPB / 4; e += 128) {
            int n  = e / (KC / 4);
            int kq = e % (KC / 4);
            int row = row0 + n; if (row >= NN) row = NN - 1;
            float4 v = *(const float4*)&Xp[row * HC + kc + kq * 4];
            Xs[kq * 4 + 0][n] = v.x;
            Xs[kq * 4 + 1][n] = v.y;
            Xs[kq * 4 + 2][n] = v.z;
            Xs[kq * 4 + 3][n] = v.w;
        }
        // stage W chunk (already k-major)
        #pragma unroll
        for (int e = tid; e < KC * OUT / 4; e += 128) {
            ((float4*)&Ws[0][0])[e] = ((const float4*)&W[kc * OUT])[e];
        }
        __syncthreads();

        #pragma unroll
        for (int k = 0; k < KC; k++) {
            float4 xa = *(const float4*)&Xs[k][ng * 8];
            float4 xb = *(const float4*)&Xs[k][ng * 8 + 4];
            float xr[8] = {xa.x, xa.y, xa.z, xa.w, xb.x, xb.y, xb.z, xb.w};
            float wr[CPT];
            {
                float4 wa = *(const float4*)&Ws[k][cg * CPT];
                wr[0] = wa.x; wr[1] = wa.y; wr[2] = wa.z; wr[3] = wa.w;
                if (CPT == 8) {
                    float4 wb = *(const float4*)&Ws[k][cg * CPT + 4];
                    wr[4] = wb.x; wr[5] = wb.y; wr[6] = wb.z; wr[7] = wb.w;
                }
            }
            #pragma unroll
            for (int i = 0; i < 8; i++)
                #pragma unroll
                for (int j = 0; j < CPT; j++)
                    acc[i][j] += xr[i] * wr[j];
        }
    }

    #pragma unroll
    for (int i = 0; i < 8; i++) {
        int row = row0 + ng * 8 + i;
        if (row < NN) {
            #pragma unroll
            for (int j = 0; j < CPT; j += 4) {
                float4 v = make_float4(acc[i][j], acc[i][j + 1], acc[i][j + 2], acc[i][j + 3]);
                *(float4*)&g_lin[row * OUT + cg * CPT + j] = v;
            }
        }
    }
}

// ---------------- per-node attention logits (warp per node) -------
__global__ void al4_kernel(const float* __restrict__ a_src, const float* __restrict__ a_dst) {
    int warp = (blockIdx.x * blockDim.x + threadIdx.x) >> 5;
    if (warp >= NN) return;
    int lane = threadIdx.x & 31;
    float4 v  = ((const float4*)(g_lin + warp * HC))[lane];
    float4 as = ((const float4*)a_src)[lane];
    float4 ad = ((const float4*)a_dst)[lane];
    float ss = v.x * as.x + v.y * as.y + v.z * as.z + v.w * as.w;
    float sd = v.x * ad.x + v.y * ad.y + v.z * ad.z + v.w * ad.w;
    #pragma unroll
    for (int o = 4; o >= 1; o >>= 1) {
        ss += __shfl_xor_sync(0xffffffff, ss, o);
        sd += __shfl_xor_sync(0xffffffff, sd, o);
    }
    if ((lane & 7) == 0) {
        int h = lane >> 3;
        g_alsrc[warp * HH + h] = ss;
        g_aldst[warp * HH + h] = sd;
    }
}

__global__ void al1_kernel(const float* __restrict__ a_src, const float* __restrict__ a_dst) {
    int warp = (blockIdx.x * blockDim.x + threadIdx.x) >> 5;
    if (warp >= NN) return;
    int lane = threadIdx.x & 31;
    float v = g_lin[warp * CC + lane];
    float ss = v * a_src[lane];
    float sd = v * a_dst[lane];
    #pragma unroll
    for (int o = 16; o >= 1; o >>= 1) {
        ss += __shfl_xor_sync(0xffffffff, ss, o);
        sd += __shfl_xor_sync(0xffffffff, sd, o);
    }
    if (lane == 0) {
        g_alsrc[warp] = ss;
        g_aldst[warp] = sd;
    }
}

// ---------------- fused GAT aggregation: warp per destination node ----------
__global__ void gat_agg4_kernel(const float* __restrict__ b, int do_elu) {
    int warp = (blockIdx.x * blockDim.x + threadIdx.x) >> 5;
    if (warp >= NN) return;
    int lane = threadIdx.x & 31;
    int d = warp;
    int start = g_rowptr[d], end = g_rowptr[d + 1];

    float4 ad = *(const float4*)&g_aldst[d * HH];

    // pass 1: leaky-relu logits + per-head max
    float4 m = make_float4(-3.0e38f, -3.0e38f, -3.0e38f, -3.0e38f);
    for (int i = start + lane; i < end; i += 32) {
        int s = g_csrc[i];
        float4 v = *(const float4*)&g_alsrc[s * HH];
        v.x += ad.x; v.y += ad.y; v.z += ad.z; v.w += ad.w;
        v.x = (v.x > 0.f) ? v.x : 0.2f * v.x;
        v.y = (v.y > 0.f) ? v.y : 0.2f * v.y;
        v.z = (v.z > 0.f) ? v.z : 0.2f * v.z;
        v.w = (v.w > 0.f) ? v.w : 0.2f * v.w;
        *(float4*)&g_w[i * HH] = v;
        m.x = fmaxf(m.x, v.x); m.y = fmaxf(m.y, v.y);
        m.z = fmaxf(m.z, v.z); m.w = fmaxf(m.w, v.w);
    }
    #pragma unroll
    for (int o = 16; o >= 1; o >>= 1) {
        m.x = fmaxf(m.x, __shfl_xor_sync(0xffffffff, m.x, o));
        m.y = fmaxf(m.y, __shfl_xor_sync(0xffffffff, m.y, o));
        m.z = fmaxf(m.z, __shfl_xor_sync(0xffffffff, m.z, o));
        m.w = fmaxf(m.w, __shfl_xor_sync(0xffffffff, m.w, o));
    }

    // pass 2: exp + per-head sum
    float4 ssum = make_float4(0.f, 0.f, 0.f, 0.f);
    for (int i = start + lane; i < end; i += 32) {
        float4 w = *(const float4*)&g_w[i * HH];
        w.x = __expf(w.x - m.x); w.y = __expf(w.y - m.y);
        w.z = __expf(w.z - m.z); w.w = __expf(w.w - m.w);
        *(float4*)&g_w[i * HH] = w;
        ssum.x += w.x; ssum.y += w.y; ssum.z += w.z; ssum.w += w.w;
    }
    #pragma unroll
    for (int o = 16; o >= 1; o >>= 1) {
        ssum.x += __shfl_xor_sync(0xffffffff, ssum.x, o);
        ssum.y += __shfl_xor_sync(0xffffffff, ssum.y, o);
        ssum.z += __shfl_xor_sync(0xffffffff, ssum.z, o);
        ssum.w += __shfl_xor_sync(0xffffffff, ssum.w, o);
    }
    float4 rd;
    rd.x = 1.f / (ssum.x + 1e-16f);
    rd.y = 1.f / (ssum.y + 1e-16f);
    rd.z = 1.f / (ssum.z + 1e-16f);
    rd.w = 1.f / (ssum.w + 1e-16f);

    // pass 3: weighted gather (lane = channel within each head)
    float a0 = 0.f, a1 = 0.f, a2 = 0.f, a3 = 0.f;
    for (int i = start; i < end; i++) {
        int s = g_csrc[i];                           // broadcast
        float4 w = *(const float4*)&g_w[i * HH];     // broadcast
        const float* hp = g_lin + s * HC;
        a0 += w.x * hp[lane];                        // 128B coalesced
        a1 += w.y * hp[32 + lane];
        a2 += w.z * hp[64 + lane];
        a3 += w.w * hp[96 + lane];
    }
    a0 = a0 * rd.x + b[lane];
    a1 = a1 * rd.y + b[32 + lane];
    a2 = a2 * rd.z + b[64 + lane];
    a3 = a3 * rd.w + b[96 + lane];
    if (do_elu) {
        a0 = (a0 > 0.f) ? a0 : (__expf(a0) - 1.f);
        a1 = (a1 > 0.f) ? a1 : (__expf(a1) - 1.f);
        a2 = (a2 > 0.f) ? a2 : (__expf(a2) - 1.f);
        a3 = (a3 > 0.f) ? a3 : (__expf(a3) - 1.f);
    }
    float* o = g_act + d * HC;
    o[lane] = a0; o[32 + lane] = a1; o[64 + lane] = a2; o[96 + lane] = a3;
}

__global__ void gat_agg1_kernel(const float* __restrict__ b) {
    int warp = (blockIdx.x * blockDim.x + threadIdx.x) >> 5;
    if (warp >= NN) return;
    int lane = threadIdx.x & 31;
    int d = warp;
    int start = g_rowptr[d], end = g_rowptr[d + 1];

    float ad = g_aldst[d];
    float m = -3.0e38f;
    for (int i = start + lane; i < end; i += 32) {
        int s = g_csrc[i];
        float v = g_alsrc[s] + ad;
        v = (v > 0.f) ? v : 0.2f * v;
        g_w[i] = v;
        m = fmaxf(m, v);
    }
    #pragma unroll
    for (int o = 16; o >= 1; o >>= 1)
        m = fmaxf(m, __shfl_xor_sync(0xffffffff, m, o));

    float ssum = 0.f;
    for (int i = start + lane; i < end; i += 32) {
        float w = __expf(g_w[i] - m);
        g_w[i] = w;
        ssum += w;
    }
    #pragma unroll
    for (int o = 16; o >= 1; o >>= 1)
        ssum += __shfl_xor_sync(0xffffffff, ssum, o);
    float rd = 1.f / (ssum + 1e-16f);

    float acc = 0.f;
    for (int i = start; i < end; i++) {
        int s = g_csrc[i];
        float w = g_w[i];
        acc += w * g_lin[s * CC + lane];
    }
    g_h3[d * CC + lane] = acc * rd + b[lane];
}

// ---------------- output head: warp per node ----------------
__global__ void head_kernel(const float* __restrict__ Wc, const float* __restrict__ bc,
                            float* __restrict__ out) {
    int warp = (blockIdx.x * blockDim.x + threadIdx.x) >> 5;
    if (warp >= NN) return;
    int lane = threadIdx.x & 31;
    float v = g_h3[warp * CC + lane];
    float o0 = v * Wc[lane * 2 + 0];
    float o1 = v * Wc[lane * 2 + 1];
    #pragma unroll
    for (int o = 16; o >= 1; o >>= 1) {
        o0 += __shfl_xor_sync(0xffffffff, o0, o);
        o1 += __shfl_xor_sync(0xffffffff, o1, o);
    }
    if (lane == 0) {
        out[warp * 2 + 0] = o0 + bc[0];
        out[warp * 2 + 1] = o1 + bc[1];
    }
    out[NN * 2 + warp * CC + lane] = v;   // link embedding copy, coalesced
}

// ---------------- launch ----------------
extern "C" void kernel_launch(void* const* d_in, const int* in_sizes, int n_in,
                              void* d_out, int out_size) {
    const float* x   = (const float*)d_in[0];
    const int*   ei  = (const int*)d_in[1];   // int32 or int64, auto-detected
    const float* W1  = (const float*)d_in[2];
    const float* a1s = (const float*)d_in[3];
    const float* a1d = (const float*)d_in[4];
    const float* b1  = (const float*)d_in[5];
    const float* W2  = (const float*)d_in[6];
    const float* a2s = (const float*)d_in[7];
    const float* a2d = (const float*)d_in[8];
    const float* b2  = (const float*)d_in[9];
    const float* W3  = (const float*)d_in[10];
    const float* a3s = (const float*)d_in[11];
    const float* a3d = (const float*)d_in[12];
    const float* b3  = (const float*)d_in[13];
    const float* Wc  = (const float*)d_in[14];
    const float* bc  = (const float*)d_in[15];
    float* out = (float*)d_out;

    const int T = 256;
    const int gE = (ETOT + T - 1) / T;
    const int gN = (NN + T - 1) / T;
    const int gW = (NN * 32 + T - 1) / T;    // warp-per-node grids

    // ---- CSR build ----
    detect_kernel<<<1, 32>>>(ei);
    zero_fill_kernel<<<gN, T>>>();
    prep_count_kernel<<<gE, T>>>(ei);
    scan_kernel<<<1, 1024>>>();
    csr_fill_kernel<<<gE, T>>>();

    // ---- layer 1 ----
    gemm_kernel<128, false><<<(NN + 63) / 64, 128>>>(x, W1);
    al4_kernel<<<gW, T>>>(a1s, a1d);
    gat_agg4_kernel<<<gW, T>>>(b1, 1);

    // ---- layer 2 ----
    gemm_kernel<128, true><<<(NN + 63) / 64, 128>>>(nullptr, W2);
    al4_kernel<<<gW, T>>>(a2s, a2d);
    gat_agg4_kernel<<<gW, T>>>(b2, 1);

    // ---- layer 3 (heads=1, no concat/activation) ----
    gemm_kernel<32, true><<<(NN + 127) / 128, 128>>>(nullptr, W3);
    al1_kernel<<<gW, T>>>(a3s, a3d);
    gat_agg1_kernel<<<gW, T>>>(b3);

    // ---- classifier head + link embedding copy ----
    head_kernel<<<gW, T>>>(Wc, bc, out);
}

// round 4
// speedup vs baseline: 3.2424x; 1.1939x over previous
#include <cuda_runtime.h>
#include <cuda_bf16.h>

// Problem constants (fixed by the dataset)
#define NN 50000
#define EE 800000
#define ETOT 850000   // EE + NN self-loops
#define HH 4
#define CC 32
#define HC 128        // HH*CC
#define NBLK ((NN + 1023) / 1024)   // 49 scan blocks

// ---------------- scratch (device globals: allocation-free) ----------------
__device__ float g_lin[NN * HC];     // linear output of current layer (messages)
__device__ float g_act[NN * HC];     // activated layer output (next layer input)
__device__ float g_h3[NN * CC];      // layer-3 output (link embedding)
__device__ float g_alsrc[NN * HH];
__device__ float g_aldst[NN * HH];
__device__ float g_w[ETOT * HH];     // per-CSR-slot logits -> exp weights
__device__ int   g_src[ETOT];
__device__ int   g_dst[ETOT];
__device__ int   g_csrc[ETOT];       // CSR: src node per slot, grouped by dst
__device__ int   g_rowptr[NN + 1];
__device__ int   g_fill[NN];
__device__ int   g_bsum[64];
__device__ int   g_is64;

// ---------------- edge prep ----------------
__global__ void detect_kernel(const int* __restrict__ buf) {
    if (blockIdx.x == 0 && threadIdx.x == 0) {
        int orv = 0;
        #pragma unroll
        for (int i = 1; i < 64; i += 2) orv |= buf[i];
        g_is64 = (orv == 0) ? 1 : 0;   // int64 little-endian -> high words zero
    }
}

__global__ void zero_fill_kernel() {
    int t = blockIdx.x * blockDim.x + threadIdx.x;
    if (t < NN) g_fill[t] = 0;
}

// decode edges + degree count in one pass
__global__ void prep_count_kernel(const int* __restrict__ buf) {
    int t = blockIdx.x * blockDim.x + threadIdx.x;
    if (t >= ETOT) return;
    int s, d;
    if (t < EE) {
        if (g_is64) {
            s = buf[2 * t];
            d = buf[2 * (EE + t)];
        } else {
            s = buf[t];
            d = buf[EE + t];
        }
    } else {
        s = d = t - EE;
    }
    g_src[t] = s;
    g_dst[t] = d;
    atomicAdd(&g_fill[d], 1);
}

// ---------------- 3-phase coalesced scan of g_fill -> g_rowptr ----------------
__global__ void block_sum_kernel() {
    __shared__ int ws[32];
    int tid = threadIdx.x;
    int idx = blockIdx.x * 1024 + tid;
    int v = (idx < NN) ? g_fill[idx] : 0;
    #pragma unroll
    for (int o = 16; o >= 1; o >>= 1) v += __shfl_xor_sync(0xffffffff, v, o);
    int lane = tid & 31, wid = tid >> 5;
    if (lane == 0) ws[wid] = v;
    __syncthreads();
    if (wid == 0) {
        int w = ws[lane];
        #pragma unroll
        for (int o = 16; o >= 1; o >>= 1) w += __shfl_xor_sync(0xffffffff, w, o);
        if (lane == 0) g_bsum[blockIdx.x] = w;
    }
}

__global__ void scan_bsum_kernel() {
    __shared__ int sm[64];
    int tid = threadIdx.x;                 // 64 threads
    int v = (tid < NBLK) ? g_bsum[tid] : 0;
    sm[tid] = v;
    __syncthreads();
    #pragma unroll
    for (int o = 1; o < 64; o <<= 1) {
        int t2 = (tid >= o) ? sm[tid - o] : 0;
        __syncthreads();
        sm[tid] += t2;
        __syncthreads();
    }
    if (tid < NBLK) g_bsum[tid] = sm[tid] - v;   // exclusive
}

__global__ void rowptr_kernel() {
    __shared__ int ws[32];
    int tid = threadIdx.x;
    int idx = blockIdx.x * 1024 + tid;
    int lane = tid & 31, wid = tid >> 5;
    int c = (idx < NN) ? g_fill[idx] : 0;
    // warp inclusive scan
    int v = c;
    #pragma unroll
    for (int o = 1; o < 32; o <<= 1) {
        int t2 = __shfl_up_sync(0xffffffff, v, o);
        if (lane >= o) v += t2;
    }
    if (lane == 31) ws[wid] = v;
    __syncthreads();
    if (wid == 0) {
        int w = ws[lane];
        #pragma unroll
        for (int o = 1; o < 32; o <<= 1) {
            int t2 = __shfl_up_sync(0xffffffff, w, o);
            if (lane >= o) w += t2;
        }
        ws[lane] = w;
    }
    __syncthreads();
    int excl = v - c + (wid > 0 ? ws[wid - 1] : 0) + g_bsum[blockIdx.x];
    if (idx < NN) {
        g_rowptr[idx] = excl;
        g_fill[idx] = excl;                // seed slot allocator
    }
    if (idx == 0) g_rowptr[NN] = ETOT;
}

__global__ void csr_fill_kernel() {
    int t = blockIdx.x * blockDim.x + threadIdx.x;
    if (t >= ETOT) return;
    int pos = atomicAdd(&g_fill[g_dst[t]], 1);
    g_csrc[pos] = g_src[t];
}

// ---------------- register-blocked GEMM: Y = X @ W ----------------
// X [NN,128], W [128,OUT]. Thread computes 8 nodes x CPT cols.
template<int OUT, bool FROMACT>
__global__ __launch_bounds__(128) void gemm_kernel(const float* __restrict__ X,
                                                   const float* __restrict__ W) {
    constexpr int NPB = (OUT == 128) ? 64 : 128;   // nodes per block
    constexpr int CPT = (OUT == 128) ? 8 : 4;      // cols per thread
    constexpr int KC  = 32;                        // k chunk
    constexpr int CGN = OUT / CPT;                 // col groups (16 or 8)

    __shared__ float Xs[KC][NPB];
    __shared__ float Ws[KC][OUT];

    const float* __restrict__ Xp = FROMACT ? g_act : X;
    const int tid = threadIdx.x;
    const int cg = tid % CGN;
    const int ng = tid / CGN;
    const int row0 = blockIdx.x * NPB;

    float acc[8][CPT];
    #pragma unroll
    for (int i = 0; i < 8; i++)
        #pragma unroll
        for (int j = 0; j < CPT; j++) acc[i][j] = 0.f;

    for (int kc = 0; kc < HC; kc += KC) {
        __syncthreads();
        // stage X chunk transposed: Xs[k][node]
        #pragma unroll
        for (int e = tid; e < KC * NPB / 4; e += 128) {
            int n  = e / (KC / 4);
            int kq = e % (KC / 4);
            int row = row0 + n; if (row >= NN) row = NN - 1;
            float4 v = *(const float4*)&Xp[row * HC + kc + kq * 4];
            Xs[kq * 4 + 0][n] = v.x;
            Xs[kq * 4 + 1][n] = v.y;
            Xs[kq * 4 + 2][n] = v.z;
            Xs[kq * 4 + 3][n] = v.w;
        }
        // stage W chunk (already k-major)
        #pragma unroll
        for (int e = tid; e < KC * OUT / 4; e += 128) {
            ((float4*)&Ws[0][0])[e] = ((const float4*)&W[kc * OUT])[e];
        }
        __syncthreads();

        #pragma unroll
        for (int k = 0; k < KC; k++) {
            float4 xa = *(const float4*)&Xs[k][ng * 8];
            float4 xb = *(const float4*)&Xs[k][ng * 8 + 4];
            float xr[8] = {xa.x, xa.y, xa.z, xa.w, xb.x, xb.y, xb.z, xb.w};
            float wr[CPT];
            {
                float4 wa = *(const float4*)&Ws[k][cg * CPT];
                wr[0] = wa.x; wr[1] = wa.y; wr[2] = wa.z; wr[3] = wa.w;
                if (CPT == 8) {
                    float4 wb = *(const float4*)&Ws[k][cg * CPT + 4];
                    wr[4] = wb.x; wr[5] = wb.y; wr[6] = wb.z; wr[7] = wb.w;
                }
            }
            #pragma unroll
            for (int i = 0; i < 8; i++)
                #pragma unroll
                for (int j = 0; j < CPT; j++)
                    acc[i][j] += xr[i] * wr[j];
        }
    }

    #pragma unroll
    for (int i = 0; i < 8; i++) {
        int row = row0 + ng * 8 + i;
        if (row < NN) {
            #pragma unroll
            for (int j = 0; j < CPT; j += 4) {
                float4 v = make_float4(acc[i][j], acc[i][j + 1], acc[i][j + 2], acc[i][j + 3]);
                *(float4*)&g_lin[row * OUT + cg * CPT + j] = v;
            }
        }
    }
}

// ---------------- per-node attention logits (warp per node) -------
__global__ void al4_kernel(const float* __restrict__ a_src, const float* __restrict__ a_dst) {
    int warp = (blockIdx.x * blockDim.x + threadIdx.x) >> 5;
    if (warp >= NN) return;
    int lane = threadIdx.x & 31;
    float4 v  = ((const float4*)(g_lin + warp * HC))[lane];
    float4 as = ((const float4*)a_src)[lane];
    float4 ad = ((const float4*)a_dst)[lane];
    float ss = v.x * as.x + v.y * as.y + v.z * as.z + v.w * as.w;
    float sd = v.x * ad.x + v.y * ad.y + v.z * ad.z + v.w * ad.w;
    #pragma unroll
    for (int o = 4; o >= 1; o >>= 1) {
        ss += __shfl_xor_sync(0xffffffff, ss, o);
        sd += __shfl_xor_sync(0xffffffff, sd, o);
    }
    if ((lane & 7) == 0) {
        int h = lane >> 3;
        g_alsrc[warp * HH + h] = ss;
        g_aldst[warp * HH + h] = sd;
    }
}

__global__ void al1_kernel(const float* __restrict__ a_src, const float* __restrict__ a_dst) {
    int warp = (blockIdx.x * blockDim.x + threadIdx.x) >> 5;
    if (warp >= NN) return;
    int lane = threadIdx.x & 31;
    float v = g_lin[warp * CC + lane];
    float ss = v * a_src[lane];
    float sd = v * a_dst[lane];
    #pragma unroll
    for (int o = 16; o >= 1; o >>= 1) {
        ss += __shfl_xor_sync(0xffffffff, ss, o);
        sd += __shfl_xor_sync(0xffffffff, sd, o);
    }
    if (lane == 0) {
        g_alsrc[warp] = ss;
        g_aldst[warp] = sd;
    }
}

// ---------------- fused GAT aggregation: warp per destination node ----------
__global__ void gat_agg4_kernel(const float* __restrict__ b, int do_elu) {
    int warp = (blockIdx.x * blockDim.x + threadIdx.x) >> 5;
    if (warp >= NN) return;
    int lane = threadIdx.x & 31;
    int d = warp;
    int start = g_rowptr[d], end = g_rowptr[d + 1];

    float4 ad = *(const float4*)&g_aldst[d * HH];

    // pass 1: leaky-relu logits + per-head max
    float4 m = make_float4(-3.0e38f, -3.0e38f, -3.0e38f, -3.0e38f);
    for (int i = start + lane; i < end; i += 32) {
        int s = g_csrc[i];
        float4 v = *(const float4*)&g_alsrc[s * HH];
        v.x += ad.x; v.y += ad.y; v.z += ad.z; v.w += ad.w;
        v.x = (v.x > 0.f) ? v.x : 0.2f * v.x;
        v.y = (v.y > 0.f) ? v.y : 0.2f * v.y;
        v.z = (v.z > 0.f) ? v.z : 0.2f * v.z;
        v.w = (v.w > 0.f) ? v.w : 0.2f * v.w;
        *(float4*)&g_w[i * HH] = v;
        m.x = fmaxf(m.x, v.x); m.y = fmaxf(m.y, v.y);
        m.z = fmaxf(m.z, v.z); m.w = fmaxf(m.w, v.w);
    }
    #pragma unroll
    for (int o = 16; o >= 1; o >>= 1) {
        m.x = fmaxf(m.x, __shfl_xor_sync(0xffffffff, m.x, o));
        m.y = fmaxf(m.y, __shfl_xor_sync(0xffffffff, m.y, o));
        m.z = fmaxf(m.z, __shfl_xor_sync(0xffffffff, m.z, o));
        m.w = fmaxf(m.w, __shfl_xor_sync(0xffffffff, m.w, o));
    }

    // pass 2: exp + per-head sum
    float4 ssum = make_float4(0.f, 0.f, 0.f, 0.f);
    for (int i = start + lane; i < end; i += 32) {
        float4 w = *(const float4*)&g_w[i * HH];
        w.x = __expf(w.x - m.x); w.y = __expf(w.y - m.y);
        w.z = __expf(w.z - m.z); w.w = __expf(w.w - m.w);
        *(float4*)&g_w[i * HH] = w;
        ssum.x += w.x; ssum.y += w.y; ssum.z += w.z; ssum.w += w.w;
    }
    #pragma unroll
    for (int o = 16; o >= 1; o >>= 1) {
        ssum.x += __shfl_xor_sync(0xffffffff, ssum.x, o);
        ssum.y += __shfl_xor_sync(0xffffffff, ssum.y, o);
        ssum.z += __shfl_xor_sync(0xffffffff, ssum.z, o);
        ssum.w += __shfl_xor_sync(0xffffffff, ssum.w, o);
    }
    float4 rd;
    rd.x = 1.f / (ssum.x + 1e-16f);
    rd.y = 1.f / (ssum.y + 1e-16f);
    rd.z = 1.f / (ssum.z + 1e-16f);
    rd.w = 1.f / (ssum.w + 1e-16f);

    // pass 3: weighted gather (lane = channel within each head)
    float a0 = 0.f, a1 = 0.f, a2 = 0.f, a3 = 0.f;
    for (int i = start; i < end; i++) {
        int s = g_csrc[i];                           // broadcast
        float4 w = *(const float4*)&g_w[i * HH];     // broadcast
        const float* hp = g_lin + s * HC;
        a0 += w.x * hp[lane];                        // 128B coalesced
        a1 += w.y * hp[32 + lane];
        a2 += w.z * hp[64 + lane];
        a3 += w.w * hp[96 + lane];
    }
    a0 = a0 * rd.x + b[lane];
    a1 = a1 * rd.y + b[32 + lane];
    a2 = a2 * rd.z + b[64 + lane];
    a3 = a3 * rd.w + b[96 + lane];
    if (do_elu) {
        a0 = (a0 > 0.f) ? a0 : (__expf(a0) - 1.f);
        a1 = (a1 > 0.f) ? a1 : (__expf(a1) - 1.f);
        a2 = (a2 > 0.f) ? a2 : (__expf(a2) - 1.f);
        a3 = (a3 > 0.f) ? a3 : (__expf(a3) - 1.f);
    }
    float* o = g_act + d * HC;
    o[lane] = a0; o[32 + lane] = a1; o[64 + lane] = a2; o[96 + lane] = a3;
}

__global__ void gat_agg1_kernel(const float* __restrict__ b) {
    int warp = (blockIdx.x * blockDim.x + threadIdx.x) >> 5;
    if (warp >= NN) return;
    int lane = threadIdx.x & 31;
    int d = warp;
    int start = g_rowptr[d], end = g_rowptr[d + 1];

    float ad = g_aldst[d];
    float m = -3.0e38f;
    for (int i = start + lane; i < end; i += 32) {
        int s = g_csrc[i];
        float v = g_alsrc[s] + ad;
        v = (v > 0.f) ? v : 0.2f * v;
        g_w[i] = v;
        m = fmaxf(m, v);
    }
    #pragma unroll
    for (int o = 16; o >= 1; o >>= 1)
        m = fmaxf(m, __shfl_xor_sync(0xffffffff, m, o));

    float ssum = 0.f;
    for (int i = start + lane; i < end; i += 32) {
        float w = __expf(g_w[i] - m);
        g_w[i] = w;
        ssum += w;
    }
    #pragma unroll
    for (int o = 16; o >= 1; o >>= 1)
        ssum += __shfl_xor_sync(0xffffffff, ssum, o);
    float rd = 1.f / (ssum + 1e-16f);

    float acc = 0.f;
    for (int i = start; i < end; i++) {
        int s = g_csrc[i];
        float w = g_w[i];
        acc += w * g_lin[s * CC + lane];
    }
    g_h3[d * CC + lane] = acc * rd + b[lane];
}

// ---------------- output head: warp per node ----------------
__global__ void head_kernel(const float* __restrict__ Wc, const float* __restrict__ bc,
                            float* __restrict__ out) {
    int warp = (blockIdx.x * blockDim.x + threadIdx.x) >> 5;
    if (warp >= NN) return;
    int lane = threadIdx.x & 31;
    float v = g_h3[warp * CC + lane];
    float o0 = v * Wc[lane * 2 + 0];
    float o1 = v * Wc[lane * 2 + 1];
    #pragma unroll
    for (int o = 16; o >= 1; o >>= 1) {
        o0 += __shfl_xor_sync(0xffffffff, o0, o);
        o1 += __shfl_xor_sync(0xffffffff, o1, o);
    }
    if (lane == 0) {
        out[warp * 2 + 0] = o0 + bc[0];
        out[warp * 2 + 1] = o1 + bc[1];
    }
    out[NN * 2 + warp * CC + lane] = v;   // link embedding copy, coalesced
}

// ---------------- launch ----------------
extern "C" void kernel_launch(void* const* d_in, const int* in_sizes, int n_in,
                              void* d_out, int out_size) {
    const float* x   = (const float*)d_in[0];
    const int*   ei  = (const int*)d_in[1];   // int32 or int64, auto-detected
    const float* W1  = (const float*)d_in[2];
    const float* a1s = (const float*)d_in[3];
    const float* a1d = (const float*)d_in[4];
    const float* b1  = (const float*)d_in[5];
    const float* W2  = (const float*)d_in[6];
    const float* a2s = (const float*)d_in[7];
    const float* a2d = (const float*)d_in[8];
    const float* b2  = (const float*)d_in[9];
    const float* W3  = (const float*)d_in[10];
    const float* a3s = (const float*)d_in[11];
    const float* a3d = (const float*)d_in[12];
    const float* b3  = (const float*)d_in[13];
    const float* Wc  = (const float*)d_in[14];
    const float* bc  = (const float*)d_in[15];
    float* out = (float*)d_out;

    const int T = 256;
    const int gE = (ETOT + T - 1) / T;
    const int gN = (NN + T - 1) / T;
    const int gW = (NN * 32 + T - 1) / T;    // warp-per-node grids

    // ---- CSR build ----
    detect_kernel<<<1, 32>>>(ei);
    zero_fill_kernel<<<gN, T>>>();
    prep_count_kernel<<<gE, T>>>(ei);
    block_sum_kernel<<<NBLK, 1024>>>();
    scan_bsum_kernel<<<1, 64>>>();
    rowptr_kernel<<<NBLK, 1024>>>();
    csr_fill_kernel<<<gE, T>>>();

    // ---- layer 1 ----
    gemm_kernel<128, false><<<(NN + 63) / 64, 128>>>(x, W1);
    al4_kernel<<<gW, T>>>(a1s, a1d);
    gat_agg4_kernel<<<gW, T>>>(b1, 1);

    // ---- layer 2 ----
    gemm_kernel<128, true><<<(NN + 63) / 64, 128>>>(nullptr, W2);
    al4_kernel<<<gW, T>>>(a2s, a2d);
    gat_agg4_kernel<<<gW, T>>>(b2, 1);

    // ---- layer 3 (heads=1, no concat/activation) ----
    gemm_kernel<32, true><<<(NN + 127) / 128, 128>>>(nullptr, W3);
    al1_kernel<<<gW, T>>>(a3s, a3d);
    gat_agg1_kernel<<<gW, T>>>(b3);

    // ---- classifier head + link embedding copy ----
    head_kernel<<<gW, T>>>(Wc, bc, out);
}

// round 5
// speedup vs baseline: 3.4520x; 1.0646x over previous
#include <cuda_runtime.h>
#include <cuda_bf16.h>

// Problem constants (fixed by the dataset)
#define NN 50000
#define EE 800000
#define ETOT 850000   // EE + NN self-loops
#define HH 4
#define CC 32
#define HC 128        // HH*CC
#define NBLK ((NN + 1023) / 1024)   // 49 scan blocks

// ---------------- scratch (device globals: allocation-free) ----------------
__device__ float g_lin[NN * HC];     // linear output of current layer (messages)
__device__ float g_act[NN * HC];     // activated layer output (next layer input)
__device__ float g_alsrc[NN * HH];
__device__ float g_aldst[NN * HH];
__device__ float g_gmax[HH];         // global max of alsrc per head (softmax shift)
__device__ int   g_src[ETOT];
__device__ int   g_dst[ETOT];
__device__ int   g_csrc[ETOT];       // CSR: src node per slot, grouped by dst
__device__ int   g_rowptr[NN + 1];
__device__ int   g_fill[NN];
__device__ int   g_bsum[64];
__device__ int   g_is64;

__device__ __forceinline__ void atomicMaxF(float* addr, float v) {
    if (v >= 0.f) atomicMax((int*)addr, __float_as_int(v));
    else          atomicMin((unsigned int*)addr, __float_as_uint(v));
}

// ---------------- edge prep ----------------
__global__ void detect_kernel(const int* __restrict__ buf) {
    if (blockIdx.x == 0 && threadIdx.x == 0) {
        int orv = 0;
        #pragma unroll
        for (int i = 1; i < 64; i += 2) orv |= buf[i];
        g_is64 = (orv == 0) ? 1 : 0;   // int64 little-endian -> high words zero
    }
}

__global__ void zero_fill_kernel() {
    int t = blockIdx.x * blockDim.x + threadIdx.x;
    if (t < NN) g_fill[t] = 0;
}

// decode edges + degree count in one pass
__global__ void prep_count_kernel(const int* __restrict__ buf) {
    int t = blockIdx.x * blockDim.x + threadIdx.x;
    if (t >= ETOT) return;
    int s, d;
    if (t < EE) {
        if (g_is64) {
            s = buf[2 * t];
            d = buf[2 * (EE + t)];
        } else {
            s = buf[t];
            d = buf[EE + t];
        }
    } else {
        s = d = t - EE;
    }
    g_src[t] = s;
    g_dst[t] = d;
    atomicAdd(&g_fill[d], 1);
}

// ---------------- 3-phase coalesced scan of g_fill -> g_rowptr ----------------
__global__ void block_sum_kernel() {
    __shared__ int ws[32];
    int tid = threadIdx.x;
    int idx = blockIdx.x * 1024 + tid;
    int v = (idx < NN) ? g_fill[idx] : 0;
    #pragma unroll
    for (int o = 16; o >= 1; o >>= 1) v += __shfl_xor_sync(0xffffffff, v, o);
    int lane = tid & 31, wid = tid >> 5;
    if (lane == 0) ws[wid] = v;
    __syncthreads();
    if (wid == 0) {
        int w = ws[lane];
        #pragma unroll
        for (int o = 16; o >= 1; o >>= 1) w += __shfl_xor_sync(0xffffffff, w, o);
        if (lane == 0) g_bsum[blockIdx.x] = w;
    }
}

__global__ void scan_bsum_kernel() {
    __shared__ int sm[64];
    int tid = threadIdx.x;                 // 64 threads
    int v = (tid < NBLK) ? g_bsum[tid] : 0;
    sm[tid] = v;
    __syncthreads();
    #pragma unroll
    for (int o = 1; o < 64; o <<= 1) {
        int t2 = (tid >= o) ? sm[tid - o] : 0;
        __syncthreads();
        sm[tid] += t2;
        __syncthreads();
    }
    if (tid < NBLK) g_bsum[tid] = sm[tid] - v;   // exclusive
}

__global__ void rowptr_kernel() {
    __shared__ int ws[32];
    int tid = threadIdx.x;
    int idx = blockIdx.x * 1024 + tid;
    int lane = tid & 31, wid = tid >> 5;
    int c = (idx < NN) ? g_fill[idx] : 0;
    int v = c;
    #pragma unroll
    for (int o = 1; o < 32; o <<= 1) {
        int t2 = __shfl_up_sync(0xffffffff, v, o);
        if (lane >= o) v += t2;
    }
    if (lane == 31) ws[wid] = v;
    __syncthreads();
    if (wid == 0) {
        int w = ws[lane];
        #pragma unroll
        for (int o = 1; o < 32; o <<= 1) {
            int t2 = __shfl_up_sync(0xffffffff, w, o);
            if (lane >= o) w += t2;
        }
        ws[lane] = w;
    }
    __syncthreads();
    int excl = v - c + (wid > 0 ? ws[wid - 1] : 0) + g_bsum[blockIdx.x];
    if (idx < NN) {
        g_rowptr[idx] = excl;
        g_fill[idx] = excl;                // seed slot allocator
    }
    if (idx == 0) g_rowptr[NN] = ETOT;
}

__global__ void csr_fill_kernel() {
    int t = blockIdx.x * blockDim.x + threadIdx.x;
    if (t >= ETOT) return;
    int pos = atomicAdd(&g_fill[g_dst[t]], 1);
    g_csrc[pos] = g_src[t];
}

// ---------------- register-blocked GEMM: Y = X @ W ----------------
template<int OUT, bool FROMACT>
__global__ __launch_bounds__(128) void gemm_kernel(const float* __restrict__ X,
                                                   const float* __restrict__ W) {
    constexpr int NPB = (OUT == 128) ? 64 : 128;   // nodes per block
    constexpr int CPT = (OUT == 128) ? 8 : 4;      // cols per thread
    constexpr int KC  = 32;
    constexpr int CGN = OUT / CPT;

    __shared__ float Xs[KC][NPB];
    __shared__ float Ws[KC][OUT];

    // reset per-layer global max (runs before the al kernel of this layer)
    if (blockIdx.x == 0 && threadIdx.x < HH) g_gmax[threadIdx.x] = -3.0e38f;

    const float* __restrict__ Xp = FROMACT ? g_act : X;
    const int tid = threadIdx.x;
    const int cg = tid % CGN;
    const int ng = tid / CGN;
    const int row0 = blockIdx.x * NPB;

    float acc[8][CPT];
    #pragma unroll
    for (int i = 0; i < 8; i++)
        #pragma unroll
        for (int j = 0; j < CPT; j++) acc[i][j] = 0.f;

    for (int kc = 0; kc < HC; kc += KC) {
        __syncthreads();
        #pragma unroll
        for (int e = tid; e < KC * NPB / 4; e += 128) {
            int n  = e / (KC / 4);
            int kq = e % (KC / 4);
            int row = row0 + n; if (row >= NN) row = NN - 1;
            float4 v = *(const float4*)&Xp[row * HC + kc + kq * 4];
            Xs[kq * 4 + 0][n] = v.x;
            Xs[kq * 4 + 1][n] = v.y;
            Xs[kq * 4 + 2][n] = v.z;
            Xs[kq * 4 + 3][n] = v.w;
        }
        #pragma unroll
        for (int e = tid; e < KC * OUT / 4; e += 128) {
            ((float4*)&Ws[0][0])[e] = ((const float4*)&W[kc * OUT])[e];
        }
        __syncthreads();

        #pragma unroll
        for (int k = 0; k < KC; k++) {
            float4 xa = *(const float4*)&Xs[k][ng * 8];
            float4 xb = *(const float4*)&Xs[k][ng * 8 + 4];
            float xr[8] = {xa.x, xa.y, xa.z, xa.w, xb.x, xb.y, xb.z, xb.w};
            float wr[CPT];
            {
                float4 wa = *(const float4*)&Ws[k][cg * CPT];
                wr[0] = wa.x; wr[1] = wa.y; wr[2] = wa.z; wr[3] = wa.w;
                if (CPT == 8) {
                    float4 wb = *(const float4*)&Ws[k][cg * CPT + 4];
                    wr[4] = wb.x; wr[5] = wb.y; wr[6] = wb.z; wr[7] = wb.w;
                }
            }
            #pragma unroll
            for (int i = 0; i < 8; i++)
                #pragma unroll
                for (int j = 0; j < CPT; j++)
                    acc[i][j] += xr[i] * wr[j];
        }
    }

    #pragma unroll
    for (int i = 0; i < 8; i++) {
        int row = row0 + ng * 8 + i;
        if (row < NN) {
            #pragma unroll
            for (int j = 0; j < CPT; j += 4) {
                float4 v = make_float4(acc[i][j], acc[i][j + 1], acc[i][j + 2], acc[i][j + 3]);
                *(float4*)&g_lin[row * OUT + cg * CPT + j] = v;
            }
        }
    }
}

// ---------------- per-node attention logits (+ global src-max) -------
__global__ void al4_kernel(const float* __restrict__ a_src, const float* __restrict__ a_dst) {
    __shared__ float smax[HH];
    int tid = threadIdx.x;
    if (tid < HH) smax[tid] = -3.0e38f;
    __syncthreads();

    int warp = (blockIdx.x * blockDim.x + tid) >> 5;
    int lane = tid & 31;
    if (warp < NN) {
        float4 v  = ((const float4*)(g_lin + warp * HC))[lane];
        float4 as = ((const float4*)a_src)[lane];
        float4 ad = ((const float4*)a_dst)[lane];
        float ss = v.x * as.x + v.y * as.y + v.z * as.z + v.w * as.w;
        float sd = v.x * ad.x + v.y * ad.y + v.z * ad.z + v.w * ad.w;
        #pragma unroll
        for (int o = 4; o >= 1; o >>= 1) {
            ss += __shfl_xor_sync(0xffffffff, ss, o);
            sd += __shfl_xor_sync(0xffffffff, sd, o);
        }
        if ((lane & 7) == 0) {
            int h = lane >> 3;
            g_alsrc[warp * HH + h] = ss;
            g_aldst[warp * HH + h] = sd;
            atomicMaxF(&smax[h], ss);      // shared atomic (cheap)
        }
    }
    __syncthreads();
    if (tid < HH) atomicMaxF(&g_gmax[tid], smax[tid]);
}

__global__ void al1_kernel(const float* __restrict__ a_src, const float* __restrict__ a_dst) {
    __shared__ float smax;
    int tid = threadIdx.x;
    if (tid == 0) smax = -3.0e38f;
    __syncthreads();

    int warp = (blockIdx.x * blockDim.x + tid) >> 5;
    int lane = tid & 31;
    if (warp < NN) {
        float v = g_lin[warp * CC + lane];
        float ss = v * a_src[lane];
        float sd = v * a_dst[lane];
        #pragma unroll
        for (int o = 16; o >= 1; o >>= 1) {
            ss += __shfl_xor_sync(0xffffffff, ss, o);
            sd += __shfl_xor_sync(0xffffffff, sd, o);
        }
        if (lane == 0) {
            g_alsrc[warp] = ss;
            g_aldst[warp] = sd;
            atomicMaxF(&smax, ss);
        }
    }
    __syncthreads();
    if (tid == 0) atomicMaxF(&g_gmax[0], smax);
}

// ---------------- single-pass fused GAT aggregation (warp per dst) ----------
// logits+exp lane-parallel, staged via smem; weighted gather + denom in one loop
__global__ __launch_bounds__(256) void gat_agg4_kernel(const float* __restrict__ b, int do_elu) {
    __shared__ int    ss[8][32];
    __shared__ float4 ww[8][32];

    int warp = (blockIdx.x * blockDim.x + threadIdx.x) >> 5;
    if (warp >= NN) return;
    int lane = threadIdx.x & 31;
    int wslot = (threadIdx.x >> 5) & 7;
    int d = warp;
    int start = g_rowptr[d], end = g_rowptr[d + 1];

    float4 ad = *(const float4*)&g_aldst[d * HH];
    float4 gm = *(const float4*)&g_gmax[0];
    // per-dst softmax shift: upper bound of leakyrelu(alsrc + ad)
    float4 m;
    m.x = gm.x + ad.x; m.x = (m.x > 0.f) ? m.x : 0.2f * m.x;
    m.y = gm.y + ad.y; m.y = (m.y > 0.f) ? m.y : 0.2f * m.y;
    m.z = gm.z + ad.z; m.z = (m.z > 0.f) ? m.z : 0.2f * m.z;
    m.w = gm.w + ad.w; m.w = (m.w > 0.f) ? m.w : 0.2f * m.w;

    float4 denom = make_float4(0.f, 0.f, 0.f, 0.f);
    float a0 = 0.f, a1 = 0.f, a2 = 0.f, a3 = 0.f;

    for (int base = start; base < end; base += 32) {
        int i = base + lane;
        float4 w = make_float4(0.f, 0.f, 0.f, 0.f);
        int s = 0;
        if (i < end) {
            s = g_csrc[i];
            float4 v = *(const float4*)&g_alsrc[s * HH];
            v.x += ad.x; v.y += ad.y; v.z += ad.z; v.w += ad.w;
            v.x = (v.x > 0.f) ? v.x : 0.2f * v.x;
            v.y = (v.y > 0.f) ? v.y : 0.2f * v.y;
            v.z = (v.z > 0.f) ? v.z : 0.2f * v.z;
            v.w = (v.w > 0.f) ? v.w : 0.2f * v.w;
            w.x = __expf(v.x - m.x);
            w.y = __expf(v.y - m.y);
            w.z = __expf(v.z - m.z);
            w.w = __expf(v.w - m.w);
        }
        denom.x += w.x; denom.y += w.y; denom.z += w.z; denom.w += w.w;
        ss[wslot][lane] = s;
        ww[wslot][lane] = w;
        __syncwarp();
        int n = min(32, end - base);
        for (int j = 0; j < n; j++) {
            int sj = ss[wslot][j];
            float4 wj = ww[wslot][j];
            const float* hp = g_lin + sj * HC;
            a0 += wj.x * hp[lane];          // 128B coalesced gathers
            a1 += wj.y * hp[32 + lane];
            a2 += wj.z * hp[64 + lane];
            a3 += wj.w * hp[96 + lane];
        }
        __syncwarp();
    }

    #pragma unroll
    for (int o = 16; o >= 1; o >>= 1) {
        denom.x += __shfl_xor_sync(0xffffffff, denom.x, o);
        denom.y += __shfl_xor_sync(0xffffffff, denom.y, o);
        denom.z += __shfl_xor_sync(0xffffffff, denom.z, o);
        denom.w += __shfl_xor_sync(0xffffffff, denom.w, o);
    }
    a0 = a0 / (denom.x + 1e-16f) + b[lane];
    a1 = a1 / (denom.y + 1e-16f) + b[32 + lane];
    a2 = a2 / (denom.z + 1e-16f) + b[64 + lane];
    a3 = a3 / (denom.w + 1e-16f) + b[96 + lane];
    if (do_elu) {
        a0 = (a0 > 0.f) ? a0 : (__expf(a0) - 1.f);
        a1 = (a1 > 0.f) ? a1 : (__expf(a1) - 1.f);
        a2 = (a2 > 0.f) ? a2 : (__expf(a2) - 1.f);
        a3 = (a3 > 0.f) ? a3 : (__expf(a3) - 1.f);
    }
    float* o = g_act + d * HC;
    o[lane] = a0; o[32 + lane] = a1; o[64 + lane] = a2; o[96 + lane] = a3;
}

// layer 3 (H=1) fused with classifier head + embedding write
__global__ __launch_bounds__(256) void gat_agg1_head_kernel(
        const float* __restrict__ b, const float* __restrict__ Wc,
        const float* __restrict__ bc, float* __restrict__ out) {
    __shared__ int   ss[8][32];
    __shared__ float ww[8][32];

    int warp = (blockIdx.x * blockDim.x + threadIdx.x) >> 5;
    if (warp >= NN) return;
    int lane = threadIdx.x & 31;
    int wslot = (threadIdx.x >> 5) & 7;
    int d = warp;
    int start = g_rowptr[d], end = g_rowptr[d + 1];

    float ad = g_aldst[d];
    float gm = g_gmax[0];
    float m = gm + ad; m = (m > 0.f) ? m : 0.2f * m;

    float denom = 0.f;
    float acc = 0.f;

    for (int base = start; base < end; base += 32) {
        int i = base + lane;
        float w = 0.f;
        int s = 0;
        if (i < end) {
            s = g_csrc[i];
            float v = g_alsrc[s] + ad;
            v = (v > 0.f) ? v : 0.2f * v;
            w = __expf(v - m);
        }
        denom += w;
        ss[wslot][lane] = s;
        ww[wslot][lane] = w;
        __syncwarp();
        int n = min(32, end - base);
        for (int j = 0; j < n; j++) {
            acc += ww[wslot][j] * g_lin[ss[wslot][j] * CC + lane];
        }
        __syncwarp();
    }
    #pragma unroll
    for (int o = 16; o >= 1; o >>= 1)
        denom += __shfl_xor_sync(0xffffffff, denom, o);

    float h = acc / (denom + 1e-16f) + b[lane];

    // link embedding (coalesced)
    out[NN * 2 + d * CC + lane] = h;

    // classifier head
    float o0 = h * Wc[lane * 2 + 0];
    float o1 = h * Wc[lane * 2 + 1];
    #pragma unroll
    for (int o = 16; o >= 1; o >>= 1) {
        o0 += __shfl_xor_sync(0xffffffff, o0, o);
        o1 += __shfl_xor_sync(0xffffffff, o1, o);
    }
    if (lane == 0) {
        out[d * 2 + 0] = o0 + bc[0];
        out[d * 2 + 1] = o1 + bc[1];
    }
}

// ---------------- launch ----------------
extern "C" void kernel_launch(void* const* d_in, const int* in_sizes, int n_in,
                              void* d_out, int out_size) {
    const float* x   = (const float*)d_in[0];
    const int*   ei  = (const int*)d_in[1];
    const float* W1  = (const float*)d_in[2];
    const float* a1s = (const float*)d_in[3];
    const float* a1d = (const float*)d_in[4];
    const float* b1  = (const float*)d_in[5];
    const float* W2  = (const float*)d_in[6];
    const float* a2s = (const float*)d_in[7];
    const float* a2d = (const float*)d_in[8];
    const float* b2  = (const float*)d_in[9];
    const float* W3  = (const float*)d_in[10];
    const float* a3s = (const float*)d_in[11];
    const float* a3d = (const float*)d_in[12];
    const float* b3  = (const float*)d_in[13];
    const float* Wc  = (const float*)d_in[14];
    const float* bc  = (const float*)d_in[15];
    float* out = (float*)d_out;

    const int T = 256;
    const int gE = (ETOT + T - 1) / T;
    const int gN = (NN + T - 1) / T;
    const int gW = (NN * 32 + T - 1) / T;    // warp-per-node grids

    // ---- CSR build ----
    detect_kernel<<<1, 32>>>(ei);
    zero_fill_kernel<<<gN, T>>>();
    prep_count_kernel<<<gE, T>>>(ei);
    block_sum_kernel<<<NBLK, 1024>>>();
    scan_bsum_kernel<<<1, 64>>>();
    rowptr_kernel<<<NBLK, 1024>>>();
    csr_fill_kernel<<<gE, T>>>();

    // ---- layer 1 ----
    gemm_kernel<128, false><<<(NN + 63) / 64, 128>>>(x, W1);
    al4_kernel<<<gW, T>>>(a1s, a1d);
    gat_agg4_kernel<<<gW, T>>>(b1, 1);

    // ---- layer 2 ----
    gemm_kernel<128, true><<<(NN + 63) / 64, 128>>>(nullptr, W2);
    al4_kernel<<<gW, T>>>(a2s, a2d);
    gat_agg4_kernel<<<gW, T>>>(b2, 1);

    // ---- layer 3 (heads=1) + classifier head ----
    gemm_kernel<32, true><<<(NN + 127) / 128, 128>>>(nullptr, W3);
    al1_kernel<<<gW, T>>>(a3s, a3d);
    gat_agg1_head_kernel<<<gW, T>>>(b3, Wc, bc, out);
}

// round 6
// speedup vs baseline: 3.6910x; 1.0692x over previous
#include <cuda_runtime.h>
#include <cuda_bf16.h>

// Problem constants (fixed by the dataset)
#define NN 50000
#define EE 800000
#define ETOT 850000   // EE + NN self-loops
#define HH 4
#define CC 32
#define HC 128        // HH*CC
#define NBLK ((NN + 1023) / 1024)   // 49 scan blocks

// ---------------- scratch (device globals: allocation-free) ----------------
__device__ float g_lin[NN * HC];
__device__ float g_act[NN * HC];
__device__ float g_alsrc[NN * HH];
__device__ float g_aldst[NN * HH];
__device__ __align__(16) float g_gmax[12];   // per-layer (3) x per-head (4) softmax shift
__device__ int   g_src[ETOT];
__device__ int   g_dst[ETOT];
__device__ int   g_csrc[ETOT];
__device__ int   g_rowptr[NN + 1];
__device__ int   g_fill[NN];
__device__ int   g_bsum[64];
__device__ int   g_is64;

__device__ __forceinline__ void atomicMaxF(float* addr, float v) {
    if (v >= 0.f) atomicMax((int*)addr, __float_as_int(v));
    else          atomicMin((unsigned int*)addr, __float_as_uint(v));
}

// ---- packed f32x2 helpers (FFMA2 path, sm_103a) ----
__device__ __forceinline__ unsigned long long pack2(float x) {
    unsigned long long r;
    asm("mov.b64 %0, {%1, %2};" : "=l"(r) : "f"(x), "f"(x));
    return r;
}
__device__ __forceinline__ void fma2(unsigned long long& d, unsigned long long a,
                                     unsigned long long b) {
    asm("fma.rn.f32x2 %0, %1, %2, %0;" : "+l"(d) : "l"(a), "l"(b));
}
__device__ __forceinline__ float2 unpack2(unsigned long long v) {
    float lo, hi;
    asm("mov.b64 {%0, %1}, %2;" : "=f"(lo), "=f"(hi) : "l"(v));
    return make_float2(lo, hi);
}

// ---------------- edge prep ----------------
__global__ void detect_kernel(const int* __restrict__ buf) {
    if (blockIdx.x == 0 && threadIdx.x == 0) {
        int orv = 0;
        #pragma unroll
        for (int i = 1; i < 64; i += 2) orv |= buf[i];
        g_is64 = (orv == 0) ? 1 : 0;
    }
    if (blockIdx.x == 0 && threadIdx.x < 12) g_gmax[threadIdx.x] = -3.0e38f;
}

__global__ void zero_fill_kernel() {
    int t = blockIdx.x * blockDim.x + threadIdx.x;
    if (t < NN) g_fill[t] = 0;
}

__global__ void prep_count_kernel(const int* __restrict__ buf) {
    int t = blockIdx.x * blockDim.x + threadIdx.x;
    if (t >= ETOT) return;
    int s, d;
    if (t < EE) {
        if (g_is64) {
            s = buf[2 * t];
            d = buf[2 * (EE + t)];
        } else {
            s = buf[t];
            d = buf[EE + t];
        }
    } else {
        s = d = t - EE;
    }
    g_src[t] = s;
    g_dst[t] = d;
    atomicAdd(&g_fill[d], 1);
}

// ---------------- 3-phase coalesced scan ----------------
__global__ void block_sum_kernel() {
    __shared__ int ws[32];
    int tid = threadIdx.x;
    int idx = blockIdx.x * 1024 + tid;
    int v = (idx < NN) ? g_fill[idx] : 0;
    #pragma unroll
    for (int o = 16; o >= 1; o >>= 1) v += __shfl_xor_sync(0xffffffff, v, o);
    int lane = tid & 31, wid = tid >> 5;
    if (lane == 0) ws[wid] = v;
    __syncthreads();
    if (wid == 0) {
        int w = ws[lane];
        #pragma unroll
        for (int o = 16; o >= 1; o >>= 1) w += __shfl_xor_sync(0xffffffff, w, o);
        if (lane == 0) g_bsum[blockIdx.x] = w;
    }
}

__global__ void scan_bsum_kernel() {
    __shared__ int sm[64];
    int tid = threadIdx.x;
    int v = (tid < NBLK) ? g_bsum[tid] : 0;
    sm[tid] = v;
    __syncthreads();
    #pragma unroll
    for (int o = 1; o < 64; o <<= 1) {
        int t2 = (tid >= o) ? sm[tid - o] : 0;
        __syncthreads();
        sm[tid] += t2;
        __syncthreads();
    }
    if (tid < NBLK) g_bsum[tid] = sm[tid] - v;
}

__global__ void rowptr_kernel() {
    __shared__ int ws[32];
    int tid = threadIdx.x;
    int idx = blockIdx.x * 1024 + tid;
    int lane = tid & 31, wid = tid >> 5;
    int c = (idx < NN) ? g_fill[idx] : 0;
    int v = c;
    #pragma unroll
    for (int o = 1; o < 32; o <<= 1) {
        int t2 = __shfl_up_sync(0xffffffff, v, o);
        if (lane >= o) v += t2;
    }
    if (lane == 31) ws[wid] = v;
    __syncthreads();
    if (wid == 0) {
        int w = ws[lane];
        #pragma unroll
        for (int o = 1; o < 32; o <<= 1) {
            int t2 = __shfl_up_sync(0xffffffff, w, o);
            if (lane >= o) w += t2;
        }
        ws[lane] = w;
    }
    __syncthreads();
    int excl = v - c + (wid > 0 ? ws[wid - 1] : 0) + g_bsum[blockIdx.x];
    if (idx < NN) {
        g_rowptr[idx] = excl;
        g_fill[idx] = excl;
    }
    if (idx == 0) g_rowptr[NN] = ETOT;
}

__global__ void csr_fill_kernel() {
    int t = blockIdx.x * blockDim.x + threadIdx.x;
    if (t >= ETOT) return;
    int pos = atomicAdd(&g_fill[g_dst[t]], 1);
    g_csrc[pos] = g_src[t];
}

// ---------------- GEMM (FFMA2) + fused attention logits ----------------
// Y = X@W; epilogue computes al_src/al_dst per (node,head) + global src max.
template<int OUT, bool FROMACT>
__global__ __launch_bounds__(128) void gemm_al_kernel(
        const float* __restrict__ X, const float* __restrict__ W,
        const float* __restrict__ a_src, const float* __restrict__ a_dst,
        int gslot) {
    constexpr int NPB = (OUT == 128) ? 64 : 128;
    constexpr int CPT = (OUT == 128) ? 8 : 4;
    constexpr int CP2 = CPT / 2;
    constexpr int CGN = OUT / CPT;                 // 16 or 8
    constexpr int KC  = 32;
    constexpr int NH  = (OUT == 128) ? 4 : 1;      // heads this layer

    __shared__ __align__(16) float Xs[KC][NPB];
    __shared__ __align__(16) float Ws[KC][OUT];
    __shared__ float smax[NH];

    const float* __restrict__ Xp = FROMACT ? g_act : X;
    const int tid = threadIdx.x;
    const int cg = tid % CGN;
    const int ng = tid / CGN;
    const int row0 = blockIdx.x * NPB;

    if (tid < NH) smax[tid] = -3.0e38f;

    unsigned long long acc2[8][CP2];
    #pragma unroll
    for (int i = 0; i < 8; i++)
        #pragma unroll
        for (int j = 0; j < CP2; j++) acc2[i][j] = 0ull;

    for (int kc = 0; kc < HC; kc += KC) {
        __syncthreads();
        #pragma unroll
        for (int e = tid; e < KC * NPB / 4; e += 128) {
            int n  = e / (KC / 4);
            int kq = e % (KC / 4);
            int row = row0 + n; if (row >= NN) row = NN - 1;
            float4 v = *(const float4*)&Xp[row * HC + kc + kq * 4];
            Xs[kq * 4 + 0][n] = v.x;
            Xs[kq * 4 + 1][n] = v.y;
            Xs[kq * 4 + 2][n] = v.z;
            Xs[kq * 4 + 3][n] = v.w;
        }
        #pragma unroll
        for (int e = tid; e < KC * OUT / 4; e += 128) {
            ((float4*)&Ws[0][0])[e] = ((const float4*)&W[kc * OUT])[e];
        }
        __syncthreads();

        #pragma unroll
        for (int k = 0; k < KC; k++) {
            float4 xa = *(const float4*)&Xs[k][ng * 8];
            float4 xb = *(const float4*)&Xs[k][ng * 8 + 4];
            unsigned long long xd[8];
            xd[0] = pack2(xa.x); xd[1] = pack2(xa.y);
            xd[2] = pack2(xa.z); xd[3] = pack2(xa.w);
            xd[4] = pack2(xb.x); xd[5] = pack2(xb.y);
            xd[6] = pack2(xb.z); xd[7] = pack2(xb.w);

            unsigned long long wp[CP2];
            {
                double2 w0 = *(const double2*)&Ws[k][cg * CPT];
                wp[0] = __double_as_longlong(w0.x);
                wp[1] = __double_as_longlong(w0.y);
                if (CP2 == 4) {
                    double2 w1 = *(const double2*)&Ws[k][cg * CPT + 4];
                    wp[2] = __double_as_longlong(w1.x);
                    wp[3] = __double_as_longlong(w1.y);
                }
            }
            #pragma unroll
            for (int i = 0; i < 8; i++)
                #pragma unroll
                for (int j = 0; j < CP2; j++)
                    fma2(acc2[i][j], xd[i], wp[j]);
        }
    }

    // unpack accumulators
    float acc[8][CPT];
    #pragma unroll
    for (int i = 0; i < 8; i++)
        #pragma unroll
        for (int j = 0; j < CP2; j++) {
            float2 v = unpack2(acc2[i][j]);
            acc[i][2 * j] = v.x;
            acc[i][2 * j + 1] = v.y;
        }

    // store Y
    #pragma unroll
    for (int i = 0; i < 8; i++) {
        int row = row0 + ng * 8 + i;
        if (row < NN) {
            #pragma unroll
            for (int j = 0; j < CPT; j += 4) {
                float4 v = make_float4(acc[i][j], acc[i][j + 1], acc[i][j + 2], acc[i][j + 3]);
                *(float4*)&g_lin[row * OUT + cg * CPT + j] = v;
            }
        }
    }

    // ---- fused al: per-thread partial dot with a_src/a_dst over owned cols ----
    float asv[CPT], adv[CPT];
    {
        float4 a0 = *(const float4*)&a_src[cg * CPT];
        asv[0] = a0.x; asv[1] = a0.y; asv[2] = a0.z; asv[3] = a0.w;
        float4 d0 = *(const float4*)&a_dst[cg * CPT];
        adv[0] = d0.x; adv[1] = d0.y; adv[2] = d0.z; adv[3] = d0.w;
        if (CPT == 8) {
            float4 a1 = *(const float4*)&a_src[cg * CPT + 4];
            asv[4] = a1.x; asv[5] = a1.y; asv[6] = a1.z; asv[7] = a1.w;
            float4 d1 = *(const float4*)&a_dst[cg * CPT + 4];
            adv[4] = d1.x; adv[5] = d1.y; adv[6] = d1.z; adv[7] = d1.w;
        }
    }
    float ssp[8], sdp[8];
    #pragma unroll
    for (int i = 0; i < 8; i++) {
        float ss = 0.f, sd = 0.f;
        #pragma unroll
        for (int j = 0; j < CPT; j++) {
            ss += acc[i][j] * asv[j];
            sd += acc[i][j] * adv[j];
        }
        ssp[i] = ss; sdp[i] = sd;
    }
    // reduce across col-group lanes covering one head
    // OUT=128: head = cg>>2, reduce over 4 lanes (xor 1,2)
    // OUT=32 : single head, reduce over 8 lanes (xor 1,2,4)
    #pragma unroll
    for (int i = 0; i < 8; i++) {
        ssp[i] += __shfl_xor_sync(0xffffffff, ssp[i], 1);
        sdp[i] += __shfl_xor_sync(0xffffffff, sdp[i], 1);
        ssp[i] += __shfl_xor_sync(0xffffffff, ssp[i], 2);
        sdp[i] += __shfl_xor_sync(0xffffffff, sdp[i], 2);
        if (OUT == 32) {
            ssp[i] += __shfl_xor_sync(0xffffffff, ssp[i], 4);
            sdp[i] += __shfl_xor_sync(0xffffffff, sdp[i], 4);
        }
    }
    float lmax = -3.0e38f;
    if (OUT == 128) {
        if ((cg & 3) == 0) {
            int h = cg >> 2;
            #pragma unroll
            for (int i = 0; i < 8; i++) {
                int row = row0 + ng * 8 + i;
                if (row < NN) {
                    g_alsrc[row * HH + h] = ssp[i];
                    g_aldst[row * HH + h] = sdp[i];
                    lmax = fmaxf(lmax, ssp[i]);
                }
            }
            atomicMaxF(&smax[h], lmax);
        }
    } else {
        if (cg == 0) {
            #pragma unroll
            for (int i = 0; i < 8; i++) {
                int row = row0 + ng * 8 + i;
                if (row < NN) {
                    g_alsrc[row] = ssp[i];
                    g_aldst[row] = sdp[i];
                    lmax = fmaxf(lmax, ssp[i]);
                }
            }
            atomicMaxF(&smax[0], lmax);
        }
    }
    __syncthreads();
    if (tid < NH) atomicMaxF(&g_gmax[gslot + tid], smax[tid]);
}

// ---------------- single-pass fused GAT aggregation (warp per dst) ----------
__global__ __launch_bounds__(256) void gat_agg4_kernel(const float* __restrict__ b,
                                                       int gslot, int do_elu) {
    __shared__ int    ss[8][32];
    __shared__ float4 ww[8][32];

    int warp = (blockIdx.x * blockDim.x + threadIdx.x) >> 5;
    if (warp >= NN) return;
    int lane = threadIdx.x & 31;
    int wslot = (threadIdx.x >> 5) & 7;
    int d = warp;
    int start = g_rowptr[d], end = g_rowptr[d + 1];

    float4 ad = *(const float4*)&g_aldst[d * HH];
    float4 gm = *(const float4*)&g_gmax[gslot];
    float4 m;
    m.x = gm.x + ad.x; m.x = (m.x > 0.f) ? m.x : 0.2f * m.x;
    m.y = gm.y + ad.y; m.y = (m.y > 0.f) ? m.y : 0.2f * m.y;
    m.z = gm.z + ad.z; m.z = (m.z > 0.f) ? m.z : 0.2f * m.z;
    m.w = gm.w + ad.w; m.w = (m.w > 0.f) ? m.w : 0.2f * m.w;

    float4 denom = make_float4(0.f, 0.f, 0.f, 0.f);
    float a0 = 0.f, a1 = 0.f, a2 = 0.f, a3 = 0.f;

    for (int base = start; base < end; base += 32) {
        int i = base + lane;
        float4 w = make_float4(0.f, 0.f, 0.f, 0.f);
        int s = 0;
        if (i < end) {
            s = g_csrc[i];
            float4 v = *(const float4*)&g_alsrc[s * HH];
            v.x += ad.x; v.y += ad.y; v.z += ad.z; v.w += ad.w;
            v.x = (v.x > 0.f) ? v.x : 0.2f * v.x;
            v.y = (v.y > 0.f) ? v.y : 0.2f * v.y;
            v.z = (v.z > 0.f) ? v.z : 0.2f * v.z;
            v.w = (v.w > 0.f) ? v.w : 0.2f * v.w;
            w.x = __expf(v.x - m.x);
            w.y = __expf(v.y - m.y);
            w.z = __expf(v.z - m.z);
            w.w = __expf(v.w - m.w);
        }
        denom.x += w.x; denom.y += w.y; denom.z += w.z; denom.w += w.w;
        ss[wslot][lane] = s;
        ww[wslot][lane] = w;
        __syncwarp();
        int n = min(32, end - base);
        for (int j = 0; j < n; j++) {
            int sj = ss[wslot][j];
            float4 wj = ww[wslot][j];
            const float* hp = g_lin + sj * HC;
            a0 += wj.x * hp[lane];
            a1 += wj.y * hp[32 + lane];
            a2 += wj.z * hp[64 + lane];
            a3 += wj.w * hp[96 + lane];
        }
        __syncwarp();
    }

    #pragma unroll
    for (int o = 16; o >= 1; o >>= 1) {
        denom.x += __shfl_xor_sync(0xffffffff, denom.x, o);
        denom.y += __shfl_xor_sync(0xffffffff, denom.y, o);
        denom.z += __shfl_xor_sync(0xffffffff, denom.z, o);
        denom.w += __shfl_xor_sync(0xffffffff, denom.w, o);
    }
    a0 = a0 / (denom.x + 1e-16f) + b[lane];
    a1 = a1 / (denom.y + 1e-16f) + b[32 + lane];
    a2 = a2 / (denom.z + 1e-16f) + b[64 + lane];
    a3 = a3 / (denom.w + 1e-16f) + b[96 + lane];
    if (do_elu) {
        a0 = (a0 > 0.f) ? a0 : (__expf(a0) - 1.f);
        a1 = (a1 > 0.f) ? a1 : (__expf(a1) - 1.f);
        a2 = (a2 > 0.f) ? a2 : (__expf(a2) - 1.f);
        a3 = (a3 > 0.f) ? a3 : (__expf(a3) - 1.f);
    }
    float* o = g_act + d * HC;
    o[lane] = a0; o[32 + lane] = a1; o[64 + lane] = a2; o[96 + lane] = a3;
}

// layer 3 (H=1) fused with classifier head + embedding write
__global__ __launch_bounds__(256) void gat_agg1_head_kernel(
        const float* __restrict__ b, const float* __restrict__ Wc,
        const float* __restrict__ bc, float* __restrict__ out) {
    __shared__ int   ss[8][32];
    __shared__ float ww[8][32];

    int warp = (blockIdx.x * blockDim.x + threadIdx.x) >> 5;
    if (warp >= NN) return;
    int lane = threadIdx.x & 31;
    int wslot = (threadIdx.x >> 5) & 7;
    int d = warp;
    int start = g_rowptr[d], end = g_rowptr[d + 1];

    float ad = g_aldst[d];
    float gm = g_gmax[8];
    float m = gm + ad; m = (m > 0.f) ? m : 0.2f * m;

    float denom = 0.f;
    float acc = 0.f;

    for (int base = start; base < end; base += 32) {
        int i = base + lane;
        float w = 0.f;
        int s = 0;
        if (i < end) {
            s = g_csrc[i];
            float v = g_alsrc[s] + ad;
            v = (v > 0.f) ? v : 0.2f * v;
            w = __expf(v - m);
        }
        denom += w;
        ss[wslot][lane] = s;
        ww[wslot][lane] = w;
        __syncwarp();
        int n = min(32, end - base);
        for (int j = 0; j < n; j++) {
            acc += ww[wslot][j] * g_lin[ss[wslot][j] * CC + lane];
        }
        __syncwarp();
    }
    #pragma unroll
    for (int o = 16; o >= 1; o >>= 1)
        denom += __shfl_xor_sync(0xffffffff, denom, o);

    float h = acc / (denom + 1e-16f) + b[lane];

    out[NN * 2 + d * CC + lane] = h;

    float o0 = h * Wc[lane * 2 + 0];
    float o1 = h * Wc[lane * 2 + 1];
    #pragma unroll
    for (int o = 16; o >= 1; o >>= 1) {
        o0 += __shfl_xor_sync(0xffffffff, o0, o);
        o1 += __shfl_xor_sync(0xffffffff, o1, o);
    }
    if (lane == 0) {
        out[d * 2 + 0] = o0 + bc[0];
        out[d * 2 + 1] = o1 + bc[1];
    }
}

// ---------------- launch ----------------
extern "C" void kernel_launch(void* const* d_in, const int* in_sizes, int n_in,
                              void* d_out, int out_size) {
    const float* x   = (const float*)d_in[0];
    const int*   ei  = (const int*)d_in[1];
    const float* W1  = (const float*)d_in[2];
    const float* a1s = (const float*)d_in[3];
    const float* a1d = (const float*)d_in[4];
    const float* b1  = (const float*)d_in[5];
    const float* W2  = (const float*)d_in[6];
    const float* a2s = (const float*)d_in[7];
    const float* a2d = (const float*)d_in[8];
    const float* b2  = (const float*)d_in[9];
    const float* W3  = (const float*)d_in[10];
    const float* a3s = (const float*)d_in[11];
    const float* a3d = (const float*)d_in[12];
    const float* b3  = (const float*)d_in[13];
    const float* Wc  = (const float*)d_in[14];
    const float* bc  = (const float*)d_in[15];
    float* out = (float*)d_out;

    const int T = 256;
    const int gE = (ETOT + T - 1) / T;
    const int gN = (NN + T - 1) / T;
    const int gW = (NN * 32 + T - 1) / T;

    // ---- CSR build ----
    detect_kernel<<<1, 32>>>(ei);
    zero_fill_kernel<<<gN, T>>>();
    prep_count_kernel<<<gE, T>>>(ei);
    block_sum_kernel<<<NBLK, 1024>>>();
    scan_bsum_kernel<<<1, 64>>>();
    rowptr_kernel<<<NBLK, 1024>>>();
    csr_fill_kernel<<<gE, T>>>();

    // ---- layer 1 ----
    gemm_al_kernel<128, false><<<(NN + 63) / 64, 128>>>(x, W1, a1s, a1d, 0);
    gat_agg4_kernel<<<gW, T>>>(b1, 0, 1);

    // ---- layer 2 ----
    gemm_al_kernel<128, true><<<(NN + 63) / 64, 128>>>(nullptr, W2, a2s, a2d, 4);
    gat_agg4_kernel<<<gW, T>>>(b2, 4, 1);

    // ---- layer 3 (heads=1) + classifier head ----
    gemm_al_kernel<32, true><<<(NN + 127) / 128, 128>>>(nullptr, W3, a3s, a3d, 8);
    gat_agg1_head_kernel<<<gW, T>>>(b3, Wc, bc, out);
}

// round 7
// speedup vs baseline: 4.1042x; 1.1119x over previous
#include <cuda_runtime.h>
#include <cuda_fp16.h>

// Problem constants (fixed by the dataset)
#define NN 50000
#define EE 800000
#define ETOT 850000   // EE + NN self-loops
#define HH 4
#define CC 32
#define HC 128        // HH*CC
#define NBLK ((NN + 1023) / 1024)   // 49 scan blocks

// ---------------- scratch (device globals: allocation-free) ----------------
__device__ __align__(16) __half g_lin16[NN * HC];  // messages (fp16, gather-only)
__device__ float g_act[NN * HC];
__device__ float g_alsrc[NN * HH];
__device__ float g_aldst[NN * HH];
__device__ __align__(16) float g_gmax[12];
__device__ int   g_src[ETOT];
__device__ int   g_dst[ETOT];
__device__ int   g_csrc[ETOT];
__device__ int   g_rowptr[NN + 1];
__device__ int   g_fill[NN];
__device__ int   g_bsum[64];
__device__ int   g_is64;

__device__ __forceinline__ void atomicMaxF(float* addr, float v) {
    if (v >= 0.f) atomicMax((int*)addr, __float_as_int(v));
    else          atomicMin((unsigned int*)addr, __float_as_uint(v));
}

// ---- packed f32x2 helpers (FFMA2 path, sm_103a) ----
__device__ __forceinline__ unsigned long long pack2(float x) {
    unsigned long long r;
    asm("mov.b64 %0, {%1, %2};" : "=l"(r) : "f"(x), "f"(x));
    return r;
}
__device__ __forceinline__ void fma2(unsigned long long& d, unsigned long long a,
                                     unsigned long long b) {
    asm("fma.rn.f32x2 %0, %1, %2, %0;" : "+l"(d) : "l"(a), "l"(b));
}
__device__ __forceinline__ float2 unpack2(unsigned long long v) {
    float lo, hi;
    asm("mov.b64 {%0, %1}, %2;" : "=f"(lo), "=f"(hi) : "l"(v));
    return make_float2(lo, hi);
}

// ---------------- edge prep ----------------
__global__ void detect_kernel(const int* __restrict__ buf) {
    if (blockIdx.x == 0 && threadIdx.x == 0) {
        int orv = 0;
        #pragma unroll
        for (int i = 1; i < 64; i += 2) orv |= buf[i];
        g_is64 = (orv == 0) ? 1 : 0;
    }
    if (blockIdx.x == 0 && threadIdx.x < 12) g_gmax[threadIdx.x] = -3.0e38f;
}

__global__ void zero_fill_kernel() {
    int t = blockIdx.x * blockDim.x + threadIdx.x;
    if (t < NN) g_fill[t] = 0;
}

__global__ void prep_count_kernel(const int* __restrict__ buf) {
    int t = blockIdx.x * blockDim.x + threadIdx.x;
    if (t >= ETOT) return;
    int s, d;
    if (t < EE) {
        if (g_is64) {
            s = buf[2 * t];
            d = buf[2 * (EE + t)];
        } else {
            s = buf[t];
            d = buf[EE + t];
        }
    } else {
        s = d = t - EE;
    }
    g_src[t] = s;
    g_dst[t] = d;
    atomicAdd(&g_fill[d], 1);
}

// ---------------- 3-phase coalesced scan ----------------
__global__ void block_sum_kernel() {
    __shared__ int ws[32];
    int tid = threadIdx.x;
    int idx = blockIdx.x * 1024 + tid;
    int v = (idx < NN) ? g_fill[idx] : 0;
    #pragma unroll
    for (int o = 16; o >= 1; o >>= 1) v += __shfl_xor_sync(0xffffffff, v, o);
    int lane = tid & 31, wid = tid >> 5;
    if (lane == 0) ws[wid] = v;
    __syncthreads();
    if (wid == 0) {
        int w = ws[lane];
        #pragma unroll
        for (int o = 16; o >= 1; o >>= 1) w += __shfl_xor_sync(0xffffffff, w, o);
        if (lane == 0) g_bsum[blockIdx.x] = w;
    }
}

__global__ void scan_bsum_kernel() {
    __shared__ int sm[64];
    int tid = threadIdx.x;
    int v = (tid < NBLK) ? g_bsum[tid] : 0;
    sm[tid] = v;
    __syncthreads();
    #pragma unroll
    for (int o = 1; o < 64; o <<= 1) {
        int t2 = (tid >= o) ? sm[tid - o] : 0;
        __syncthreads();
        sm[tid] += t2;
        __syncthreads();
    }
    if (tid < NBLK) g_bsum[tid] = sm[tid] - v;
}

__global__ void rowptr_kernel() {
    __shared__ int ws[32];
    int tid = threadIdx.x;
    int idx = blockIdx.x * 1024 + tid;
    int lane = tid & 31, wid = tid >> 5;
    int c = (idx < NN) ? g_fill[idx] : 0;
    int v = c;
    #pragma unroll
    for (int o = 1; o < 32; o <<= 1) {
        int t2 = __shfl_up_sync(0xffffffff, v, o);
        if (lane >= o) v += t2;
    }
    if (lane == 31) ws[wid] = v;
    __syncthreads();
    if (wid == 0) {
        int w = ws[lane];
        #pragma unroll
        for (int o = 1; o < 32; o <<= 1) {
            int t2 = __shfl_up_sync(0xffffffff, w, o);
            if (lane >= o) w += t2;
        }
        ws[lane] = w;
    }
    __syncthreads();
    int excl = v - c + (wid > 0 ? ws[wid - 1] : 0) + g_bsum[blockIdx.x];
    if (idx < NN) {
        g_rowptr[idx] = excl;
        g_fill[idx] = excl;
    }
    if (idx == 0) g_rowptr[NN] = ETOT;
}

__global__ void csr_fill_kernel() {
    int t = blockIdx.x * blockDim.x + threadIdx.x;
    if (t >= ETOT) return;
    int pos = atomicAdd(&g_fill[g_dst[t]], 1);
    g_csrc[pos] = g_src[t];
}

// ---------------- GEMM (FFMA2) + fused attention logits ----------------
// Y = X@W stored as fp16 messages; epilogue computes al_src/al_dst + global max.
template<int OUT, bool FROMACT>
__global__ __launch_bounds__(128) void gemm_al_kernel(
        const float* __restrict__ X, const float* __restrict__ W,
        const float* __restrict__ a_src, const float* __restrict__ a_dst,
        int gslot) {
    constexpr int NPB = (OUT == 128) ? 64 : 128;
    constexpr int CPT = (OUT == 128) ? 8 : 4;
    constexpr int CP2 = CPT / 2;
    constexpr int CGN = OUT / CPT;
    constexpr int KC  = 32;
    constexpr int NH  = (OUT == 128) ? 4 : 1;

    __shared__ __align__(16) float Xs[KC][NPB];
    __shared__ __align__(16) float Ws[KC][OUT];
    __shared__ float smax[NH];

    const float* __restrict__ Xp = FROMACT ? g_act : X;
    const int tid = threadIdx.x;
    const int cg = tid % CGN;
    const int ng = tid / CGN;
    const int row0 = blockIdx.x * NPB;

    if (tid < NH) smax[tid] = -3.0e38f;

    unsigned long long acc2[8][CP2];
    #pragma unroll
    for (int i = 0; i < 8; i++)
        #pragma unroll
        for (int j = 0; j < CP2; j++) acc2[i][j] = 0ull;

    for (int kc = 0; kc < HC; kc += KC) {
        __syncthreads();
        #pragma unroll
        for (int e = tid; e < KC * NPB / 4; e += 128) {
            int n  = e / (KC / 4);
            int kq = e % (KC / 4);
            int row = row0 + n; if (row >= NN) row = NN - 1;
            float4 v = *(const float4*)&Xp[row * HC + kc + kq * 4];
            Xs[kq * 4 + 0][n] = v.x;
            Xs[kq * 4 + 1][n] = v.y;
            Xs[kq * 4 + 2][n] = v.z;
            Xs[kq * 4 + 3][n] = v.w;
        }
        #pragma unroll
        for (int e = tid; e < KC * OUT / 4; e += 128) {
            ((float4*)&Ws[0][0])[e] = ((const float4*)&W[kc * OUT])[e];
        }
        __syncthreads();

        #pragma unroll
        for (int k = 0; k < KC; k++) {
            float4 xa = *(const float4*)&Xs[k][ng * 8];
            float4 xb = *(const float4*)&Xs[k][ng * 8 + 4];
            unsigned long long xd[8];
            xd[0] = pack2(xa.x); xd[1] = pack2(xa.y);
            xd[2] = pack2(xa.z); xd[3] = pack2(xa.w);
            xd[4] = pack2(xb.x); xd[5] = pack2(xb.y);
            xd[6] = pack2(xb.z); xd[7] = pack2(xb.w);

            unsigned long long wp[CP2];
            {
                double2 w0 = *(const double2*)&Ws[k][cg * CPT];
                wp[0] = __double_as_longlong(w0.x);
                wp[1] = __double_as_longlong(w0.y);
                if (CP2 == 4) {
                    double2 w1 = *(const double2*)&Ws[k][cg * CPT + 4];
                    wp[2] = __double_as_longlong(w1.x);
                    wp[3] = __double_as_longlong(w1.y);
                }
            }
            #pragma unroll
            for (int i = 0; i < 8; i++)
                #pragma unroll
                for (int j = 0; j < CP2; j++)
                    fma2(acc2[i][j], xd[i], wp[j]);
        }
    }

    float acc[8][CPT];
    #pragma unroll
    for (int i = 0; i < 8; i++)
        #pragma unroll
        for (int j = 0; j < CP2; j++) {
            float2 v = unpack2(acc2[i][j]);
            acc[i][2 * j] = v.x;
            acc[i][2 * j + 1] = v.y;
        }

    // store messages as fp16 (half2 pairs)
    #pragma unroll
    for (int i = 0; i < 8; i++) {
        int row = row0 + ng * 8 + i;
        if (row < NN) {
            #pragma unroll
            for (int j = 0; j < CP2; j++) {
                __half2 h = __float22half2_rn(make_float2(acc[i][2 * j], acc[i][2 * j + 1]));
                *(__half2*)&g_lin16[row * OUT + cg * CPT + 2 * j] = h;
            }
        }
    }

    // ---- fused al ----
    float asv[CPT], adv[CPT];
    {
        float4 a0 = *(const float4*)&a_src[cg * CPT];
        asv[0] = a0.x; asv[1] = a0.y; asv[2] = a0.z; asv[3] = a0.w;
        float4 d0 = *(const float4*)&a_dst[cg * CPT];
        adv[0] = d0.x; adv[1] = d0.y; adv[2] = d0.z; adv[3] = d0.w;
        if (CPT == 8) {
            float4 a1 = *(const float4*)&a_src[cg * CPT + 4];
            asv[4] = a1.x; asv[5] = a1.y; asv[6] = a1.z; asv[7] = a1.w;
            float4 d1 = *(const float4*)&a_dst[cg * CPT + 4];
            adv[4] = d1.x; adv[5] = d1.y; adv[6] = d1.z; adv[7] = d1.w;
        }
    }
    float ssp[8], sdp[8];
    #pragma unroll
    for (int i = 0; i < 8; i++) {
        float ss = 0.f, sd = 0.f;
        #pragma unroll
        for (int j = 0; j < CPT; j++) {
            ss += acc[i][j] * asv[j];
            sd += acc[i][j] * adv[j];
        }
        ssp[i] = ss; sdp[i] = sd;
    }
    #pragma unroll
    for (int i = 0; i < 8; i++) {
        ssp[i] += __shfl_xor_sync(0xffffffff, ssp[i], 1);
        sdp[i] += __shfl_xor_sync(0xffffffff, sdp[i], 1);
        ssp[i] += __shfl_xor_sync(0xffffffff, ssp[i], 2);
        sdp[i] += __shfl_xor_sync(0xffffffff, sdp[i], 2);
        if (OUT == 32) {
            ssp[i] += __shfl_xor_sync(0xffffffff, ssp[i], 4);
            sdp[i] += __shfl_xor_sync(0xffffffff, sdp[i], 4);
        }
    }
    float lmax = -3.0e38f;
    if (OUT == 128) {
        if ((cg & 3) == 0) {
            int h = cg >> 2;
            #pragma unroll
            for (int i = 0; i < 8; i++) {
                int row = row0 + ng * 8 + i;
                if (row < NN) {
                    g_alsrc[row * HH + h] = ssp[i];
                    g_aldst[row * HH + h] = sdp[i];
                    lmax = fmaxf(lmax, ssp[i]);
                }
            }
            atomicMaxF(&smax[h], lmax);
        }
    } else {
        if (cg == 0) {
            #pragma unroll
            for (int i = 0; i < 8; i++) {
                int row = row0 + ng * 8 + i;
                if (row < NN) {
                    g_alsrc[row] = ssp[i];
                    g_aldst[row] = sdp[i];
                    lmax = fmaxf(lmax, ssp[i]);
                }
            }
            atomicMaxF(&smax[0], lmax);
        }
    }
    __syncthreads();
    if (tid < NH) atomicMaxF(&g_gmax[gslot + tid], smax[tid]);
}

// ---------------- single-pass fused GAT aggregation (warp per dst, fp16 gather) --
__global__ __launch_bounds__(256) void gat_agg4_kernel(const float* __restrict__ b,
                                                       int gslot, int do_elu) {
    __shared__ int    ss[8][32];
    __shared__ float4 ww[8][32];

    int warp = (blockIdx.x * blockDim.x + threadIdx.x) >> 5;
    if (warp >= NN) return;
    int lane = threadIdx.x & 31;
    int wslot = (threadIdx.x >> 5) & 7;
    int d = warp;
    int start = g_rowptr[d], end = g_rowptr[d + 1];

    float4 ad = *(const float4*)&g_aldst[d * HH];
    float4 gm = *(const float4*)&g_gmax[gslot];
    float4 m;
    m.x = gm.x + ad.x; m.x = (m.x > 0.f) ? m.x : 0.2f * m.x;
    m.y = gm.y + ad.y; m.y = (m.y > 0.f) ? m.y : 0.2f * m.y;
    m.z = gm.z + ad.z; m.z = (m.z > 0.f) ? m.z : 0.2f * m.z;
    m.w = gm.w + ad.w; m.w = (m.w > 0.f) ? m.w : 0.2f * m.w;

    const int h0 = lane >> 4;        // head for channels [2*lane, 2*lane+1]
    const int h1 = 2 + h0;           // head for channels [64+2*lane, 64+2*lane+1]

    float4 denom = make_float4(0.f, 0.f, 0.f, 0.f);
    float a0x = 0.f, a0y = 0.f, a1x = 0.f, a1y = 0.f;

    for (int base = start; base < end; base += 32) {
        int i = base + lane;
        float4 w = make_float4(0.f, 0.f, 0.f, 0.f);
        int s = 0;
        if (i < end) {
            s = g_csrc[i];
            float4 v = *(const float4*)&g_alsrc[s * HH];
            v.x += ad.x; v.y += ad.y; v.z += ad.z; v.w += ad.w;
            v.x = (v.x > 0.f) ? v.x : 0.2f * v.x;
            v.y = (v.y > 0.f) ? v.y : 0.2f * v.y;
            v.z = (v.z > 0.f) ? v.z : 0.2f * v.z;
            v.w = (v.w > 0.f) ? v.w : 0.2f * v.w;
            w.x = __expf(v.x - m.x);
            w.y = __expf(v.y - m.y);
            w.z = __expf(v.z - m.z);
            w.w = __expf(v.w - m.w);
        }
        denom.x += w.x; denom.y += w.y; denom.z += w.z; denom.w += w.w;
        ss[wslot][lane] = s;
        ww[wslot][lane] = w;
        __syncwarp();
        int n = min(32, end - base);
        for (int j = 0; j < n; j++) {
            int sj = ss[wslot][j];
            const float* wjp = (const float*)&ww[wslot][j];
            float w0 = wjp[h0];
            float w1 = wjp[h1];
            const __half2* hp = (const __half2*)(g_lin16 + sj * HC);
            float2 m0 = __half22float2(hp[lane]);        // channels 2l, 2l+1
            float2 m1 = __half22float2(hp[32 + lane]);   // channels 64+2l, 64+2l+1
            a0x += w0 * m0.x; a0y += w0 * m0.y;
            a1x += w1 * m1.x; a1y += w1 * m1.y;
        }
        __syncwarp();
    }

    #pragma unroll
    for (int o = 16; o >= 1; o >>= 1) {
        denom.x += __shfl_xor_sync(0xffffffff, denom.x, o);
        denom.y += __shfl_xor_sync(0xffffffff, denom.y, o);
        denom.z += __shfl_xor_sync(0xffffffff, denom.z, o);
        denom.w += __shfl_xor_sync(0xffffffff, denom.w, o);
    }
    float rd0 = 1.f / ((h0 == 0 ? denom.x : denom.y) + 1e-16f);
    float rd1 = 1.f / ((h1 == 2 ? denom.z : denom.w) + 1e-16f);

    float2 b0 = *(const float2*)&b[2 * lane];
    float2 b1 = *(const float2*)&b[64 + 2 * lane];
    a0x = a0x * rd0 + b0.x;
    a0y = a0y * rd0 + b0.y;
    a1x = a1x * rd1 + b1.x;
    a1y = a1y * rd1 + b1.y;
    if (do_elu) {
        a0x = (a0x > 0.f) ? a0x : (__expf(a0x) - 1.f);
        a0y = (a0y > 0.f) ? a0y : (__expf(a0y) - 1.f);
        a1x = (a1x > 0.f) ? a1x : (__expf(a1x) - 1.f);
        a1y = (a1y > 0.f) ? a1y : (__expf(a1y) - 1.f);
    }
    float* o = g_act + d * HC;
    *(float2*)&o[2 * lane] = make_float2(a0x, a0y);
    *(float2*)&o[64 + 2 * lane] = make_float2(a1x, a1y);
}

// layer 3 (H=1) fused with classifier head + embedding write
__global__ __launch_bounds__(256) void gat_agg1_head_kernel(
        const float* __restrict__ b, const float* __restrict__ Wc,
        const float* __restrict__ bc, float* __restrict__ out) {
    __shared__ int   ss[8][32];
    __shared__ float ww[8][32];

    int warp = (blockIdx.x * blockDim.x + threadIdx.x) >> 5;
    if (warp >= NN) return;
    int lane = threadIdx.x & 31;
    int wslot = (threadIdx.x >> 5) & 7;
    int d = warp;
    int start = g_rowptr[d], end = g_rowptr[d + 1];

    float ad = g_aldst[d];
    float gm = g_gmax[8];
    float m = gm + ad; m = (m > 0.f) ? m : 0.2f * m;

    float denom = 0.f;
    float acc = 0.f;

    for (int base = start; base < end; base += 32) {
        int i = base + lane;
        float w = 0.f;
        int s = 0;
        if (i < end) {
            s = g_csrc[i];
            float v = g_alsrc[s] + ad;
            v = (v > 0.f) ? v : 0.2f * v;
            w = __expf(v - m);
        }
        denom += w;
        ss[wslot][lane] = s;
        ww[wslot][lane] = w;
        __syncwarp();
        int n = min(32, end - base);
        for (int j = 0; j < n; j++) {
            acc += ww[wslot][j] * __half2float(g_lin16[ss[wslot][j] * CC + lane]);
        }
        __syncwarp();
    }
    #pragma unroll
    for (int o = 16; o >= 1; o >>= 1)
        denom += __shfl_xor_sync(0xffffffff, denom, o);

    float h = acc / (denom + 1e-16f) + b[lane];

    out[NN * 2 + d * CC + lane] = h;

    float o0 = h * Wc[lane * 2 + 0];
    float o1 = h * Wc[lane * 2 + 1];
    #pragma unroll
    for (int o = 16; o >= 1; o >>= 1) {
        o0 += __shfl_xor_sync(0xffffffff, o0, o);
        o1 += __shfl_xor_sync(0xffffffff, o1, o);
    }
    if (lane == 0) {
        out[d * 2 + 0] = o0 + bc[0];
        out[d * 2 + 1] = o1 + bc[1];
    }
}

// ---------------- launch ----------------
extern "C" void kernel_launch(void* const* d_in, const int* in_sizes, int n_in,
                              void* d_out, int out_size) {
    const float* x   = (const float*)d_in[0];
    const int*   ei  = (const int*)d_in[1];
    const float* W1  = (const float*)d_in[2];
    const float* a1s = (const float*)d_in[3];
    const float* a1d = (const float*)d_in[4];
    const float* b1  = (const float*)d_in[5];
    const float* W2  = (const float*)d_in[6];
    const float* a2s = (const float*)d_in[7];
    const float* a2d = (const float*)d_in[8];
    const float* b2  = (const float*)d_in[9];
    const float* W3  = (const float*)d_in[10];
    const float* a3s = (const float*)d_in[11];
    const float* a3d = (const float*)d_in[12];
    const float* b3  = (const float*)d_in[13];
    const float* Wc  = (const float*)d_in[14];
    const float* bc  = (const float*)d_in[15];
    float* out = (float*)d_out;

    const int T = 256;
    const int gE = (ETOT + T - 1) / T;
    const int gN = (NN + T - 1) / T;
    const int gW = (NN * 32 + T - 1) / T;

    // ---- CSR build ----
    detect_kernel<<<1, 32>>>(ei);
    zero_fill_kernel<<<gN, T>>>();
    prep_count_kernel<<<gE, T>>>(ei);
    block_sum_kernel<<<NBLK, 1024>>>();
    scan_bsum_kernel<<<1, 64>>>();
    rowptr_kernel<<<NBLK, 1024>>>();
    csr_fill_kernel<<<gE, T>>>();

    // ---- layer 1 ----
    gemm_al_kernel<128, false><<<(NN + 63) / 64, 128>>>(x, W1, a1s, a1d, 0);
    gat_agg4_kernel<<<gW, T>>>(b1, 0, 1);

    // ---- layer 2 ----
    gemm_al_kernel<128, true><<<(NN + 63) / 64, 128>>>(nullptr, W2, a2s, a2d, 4);
    gat_agg4_kernel<<<gW, T>>>(b2, 4, 1);

    // ---- layer 3 (heads=1) + classifier head ----
    gemm_al_kernel<32, true><<<(NN + 127) / 128, 128>>>(nullptr, W3, a3s, a3d, 8);
    gat_agg1_head_kernel<<<gW, T>>>(b3, Wc, bc, out);
}

// round 8
// speedup vs baseline: 4.4182x; 1.0765x over previous
#include <cuda_runtime.h>
#include <cuda_fp16.h>

// Problem constants (fixed by the dataset)
#define NN 50000
#define EE 800000
#define ETOT 850000   // EE + NN self-loops
#define HH 4
#define CC 32
#define HC 128        // HH*CC
#define NBLK ((NN + 1023) / 1024)   // 49 scan blocks

// ---------------- scratch (device globals: allocation-free) ----------------
__device__ __align__(16) __half g_lin16[NN * HC];  // messages (fp16, gather-only)
__device__ float g_act[NN * HC];
__device__ float g_alsrc[NN * HH];
__device__ float g_aldst[NN * HH];
__device__ __align__(16) float g_gmax[12];
__device__ int   g_csrc[ETOT];
__device__ int   g_rowptr[NN + 1];
__device__ int   g_fill[NN];
__device__ int   g_bsum[64];
__device__ int   g_is64;

// ---------------- streams for fork/join inside graph capture --------------
struct StreamPack {
    cudaStream_t sA, sB;
    cudaEvent_t evFork, evA, evB;
    StreamPack() {
        cudaStreamCreateWithFlags(&sA, cudaStreamNonBlocking);
        cudaStreamCreateWithFlags(&sB, cudaStreamNonBlocking);
        cudaEventCreateWithFlags(&evFork, cudaEventDisableTiming);
        cudaEventCreateWithFlags(&evA, cudaEventDisableTiming);
        cudaEventCreateWithFlags(&evB, cudaEventDisableTiming);
    }
};
static StreamPack g_sp;

__device__ __forceinline__ void atomicMaxF(float* addr, float v) {
    if (v >= 0.f) atomicMax((int*)addr, __float_as_int(v));
    else          atomicMin((unsigned int*)addr, __float_as_uint(v));
}

// ---- packed f32x2 helpers (FFMA2 path, sm_103a) ----
__device__ __forceinline__ unsigned long long pack2(float x) {
    unsigned long long r;
    asm("mov.b64 %0, {%1, %2};" : "=l"(r) : "f"(x), "f"(x));
    return r;
}
__device__ __forceinline__ void fma2(unsigned long long& d, unsigned long long a,
                                     unsigned long long b) {
    asm("fma.rn.f32x2 %0, %1, %2, %0;" : "+l"(d) : "l"(a), "l"(b));
}
__device__ __forceinline__ float2 unpack2(unsigned long long v) {
    float lo, hi;
    asm("mov.b64 {%0, %1}, %2;" : "=f"(lo), "=f"(hi) : "l"(v));
    return make_float2(lo, hi);
}

// edge decode helper (reads g_is64)
__device__ __forceinline__ void decode_edge(const int* __restrict__ buf, int t,
                                            int& s, int& d) {
    if (t < EE) {
        if (g_is64) {
            s = buf[2 * t];
            d = buf[2 * (EE + t)];
        } else {
            s = buf[t];
            d = buf[EE + t];
        }
    } else {
        s = d = t - EE;
    }
}

// ---------------- edge prep ----------------
__global__ void detect_kernel(const int* __restrict__ buf) {
    if (blockIdx.x == 0 && threadIdx.x == 0) {
        int orv = 0;
        #pragma unroll
        for (int i = 1; i < 64; i += 2) orv |= buf[i];
        g_is64 = (orv == 0) ? 1 : 0;
    }
    if (blockIdx.x == 0 && threadIdx.x < 12) g_gmax[threadIdx.x] = -3.0e38f;
}

__global__ void zero_fill_kernel() {
    int t = blockIdx.x * blockDim.x + threadIdx.x;
    if (t < NN) g_fill[t] = 0;
}

// degree count: decode dst directly from the input buffer
__global__ void count_kernel(const int* __restrict__ buf) {
    int t = blockIdx.x * blockDim.x + threadIdx.x;
    if (t >= ETOT) return;
    int d;
    if (t < EE) {
        d = g_is64 ? buf[2 * (EE + t)] : buf[EE + t];
    } else {
        d = t - EE;
    }
    atomicAdd(&g_fill[d], 1);
}

// ---------------- 3-phase coalesced scan ----------------
__global__ void block_sum_kernel() {
    __shared__ int ws[32];
    int tid = threadIdx.x;
    int idx = blockIdx.x * 1024 + tid;
    int v = (idx < NN) ? g_fill[idx] : 0;
    #pragma unroll
    for (int o = 16; o >= 1; o >>= 1) v += __shfl_xor_sync(0xffffffff, v, o);
    int lane = tid & 31, wid = tid >> 5;
    if (lane == 0) ws[wid] = v;
    __syncthreads();
    if (wid == 0) {
        int w = ws[lane];
        #pragma unroll
        for (int o = 16; o >= 1; o >>= 1) w += __shfl_xor_sync(0xffffffff, w, o);
        if (lane == 0) g_bsum[blockIdx.x] = w;
    }
}

__global__ void scan_bsum_kernel() {
    __shared__ int sm[64];
    int tid = threadIdx.x;
    int v = (tid < NBLK) ? g_bsum[tid] : 0;
    sm[tid] = v;
    __syncthreads();
    #pragma unroll
    for (int o = 1; o < 64; o <<= 1) {
        int t2 = (tid >= o) ? sm[tid - o] : 0;
        __syncthreads();
        sm[tid] += t2;
        __syncthreads();
    }
    if (tid < NBLK) g_bsum[tid] = sm[tid] - v;
}

__global__ void rowptr_kernel() {
    __shared__ int ws[32];
    int tid = threadIdx.x;
    int idx = blockIdx.x * 1024 + tid;
    int lane = tid & 31, wid = tid >> 5;
    int c = (idx < NN) ? g_fill[idx] : 0;
    int v = c;
    #pragma unroll
    for (int o = 1; o < 32; o <<= 1) {
        int t2 = __shfl_up_sync(0xffffffff, v, o);
        if (lane >= o) v += t2;
    }
    if (lane == 31) ws[wid] = v;
    __syncthreads();
    if (wid == 0) {
        int w = ws[lane];
        #pragma unroll
        for (int o = 1; o < 32; o <<= 1) {
            int t2 = __shfl_up_sync(0xffffffff, w, o);
            if (lane >= o) w += t2;
        }
        ws[lane] = w;
    }
    __syncthreads();
    int excl = v - c + (wid > 0 ? ws[wid - 1] : 0) + g_bsum[blockIdx.x];
    if (idx < NN) {
        g_rowptr[idx] = excl;
        g_fill[idx] = excl;
    }
    if (idx == 0) g_rowptr[NN] = ETOT;
}

// fill CSR: decode both endpoints directly from the input buffer
__global__ void csr_fill_kernel(const int* __restrict__ buf) {
    int t = blockIdx.x * blockDim.x + threadIdx.x;
    if (t >= ETOT) return;
    int s, d;
    decode_edge(buf, t, s, d);
    int pos = atomicAdd(&g_fill[d], 1);
    g_csrc[pos] = s;
}

// ---------------- GEMM (FFMA2) + fused attention logits ----------------
template<int OUT, bool FROMACT>
__global__ __launch_bounds__(128) void gemm_al_kernel(
        const float* __restrict__ X, const float* __restrict__ W,
        const float* __restrict__ a_src, const float* __restrict__ a_dst,
        int gslot) {
    constexpr int NPB = (OUT == 128) ? 64 : 128;
    constexpr int CPT = (OUT == 128) ? 8 : 4;
    constexpr int CP2 = CPT / 2;
    constexpr int CGN = OUT / CPT;
    constexpr int KC  = 32;
    constexpr int NH  = (OUT == 128) ? 4 : 1;

    __shared__ __align__(16) float Xs[KC][NPB];
    __shared__ __align__(16) float Ws[KC][OUT];
    __shared__ float smax[NH];

    const float* __restrict__ Xp = FROMACT ? g_act : X;
    const int tid = threadIdx.x;
    const int cg = tid % CGN;
    const int ng = tid / CGN;
    const int row0 = blockIdx.x * NPB;

    if (tid < NH) smax[tid] = -3.0e38f;

    unsigned long long acc2[8][CP2];
    #pragma unroll
    for (int i = 0; i < 8; i++)
        #pragma unroll
        for (int j = 0; j < CP2; j++) acc2[i][j] = 0ull;

    for (int kc = 0; kc < HC; kc += KC) {
        __syncthreads();
        #pragma unroll
        for (int e = tid; e < KC * NPB / 4; e += 128) {
            int n  = e / (KC / 4);
            int kq = e % (KC / 4);
            int row = row0 + n; if (row >= NN) row = NN - 1;
            float4 v = *(const float4*)&Xp[row * HC + kc + kq * 4];
            Xs[kq * 4 + 0][n] = v.x;
            Xs[kq * 4 + 1][n] = v.y;
            Xs[kq * 4 + 2][n] = v.z;
            Xs[kq * 4 + 3][n] = v.w;
        }
        #pragma unroll
        for (int e = tid; e < KC * OUT / 4; e += 128) {
            ((float4*)&Ws[0][0])[e] = ((const float4*)&W[kc * OUT])[e];
        }
        __syncthreads();

        #pragma unroll
        for (int k = 0; k < KC; k++) {
            float4 xa = *(const float4*)&Xs[k][ng * 8];
            float4 xb = *(const float4*)&Xs[k][ng * 8 + 4];
            unsigned long long xd[8];
            xd[0] = pack2(xa.x); xd[1] = pack2(xa.y);
            xd[2] = pack2(xa.z); xd[3] = pack2(xa.w);
            xd[4] = pack2(xb.x); xd[5] = pack2(xb.y);
            xd[6] = pack2(xb.z); xd[7] = pack2(xb.w);

            unsigned long long wp[CP2];
            {
                double2 w0 = *(const double2*)&Ws[k][cg * CPT];
                wp[0] = __double_as_longlong(w0.x);
                wp[1] = __double_as_longlong(w0.y);
                if (CP2 == 4) {
                    double2 w1 = *(const double2*)&Ws[k][cg * CPT + 4];
                    wp[2] = __double_as_longlong(w1.x);
                    wp[3] = __double_as_longlong(w1.y);
                }
            }
            #pragma unroll
            for (int i = 0; i < 8; i++)
                #pragma unroll
                for (int j = 0; j < CP2; j++)
                    fma2(acc2[i][j], xd[i], wp[j]);
        }
    }

    float acc[8][CPT];
    #pragma unroll
    for (int i = 0; i < 8; i++)
        #pragma unroll
        for (int j = 0; j < CP2; j++) {
            float2 v = unpack2(acc2[i][j]);
            acc[i][2 * j] = v.x;
            acc[i][2 * j + 1] = v.y;
        }

    // store messages as fp16 (half2 pairs)
    #pragma unroll
    for (int i = 0; i < 8; i++) {
        int row = row0 + ng * 8 + i;
        if (row < NN) {
            #pragma unroll
            for (int j = 0; j < CP2; j++) {
                __half2 h = __float22half2_rn(make_float2(acc[i][2 * j], acc[i][2 * j + 1]));
                *(__half2*)&g_lin16[row * OUT + cg * CPT + 2 * j] = h;
            }
        }
    }

    // ---- fused al ----
    float asv[CPT], adv[CPT];
    {
        float4 a0 = *(const float4*)&a_src[cg * CPT];
        asv[0] = a0.x; asv[1] = a0.y; asv[2] = a0.z; asv[3] = a0.w;
        float4 d0 = *(const float4*)&a_dst[cg * CPT];
        adv[0] = d0.x; adv[1] = d0.y; adv[2] = d0.z; adv[3] = d0.w;
        if (CPT == 8) {
            float4 a1 = *(const float4*)&a_src[cg * CPT + 4];
            asv[4] = a1.x; asv[5] = a1.y; asv[6] = a1.z; asv[7] = a1.w;
            float4 d1 = *(const float4*)&a_dst[cg * CPT + 4];
            adv[4] = d1.x; adv[5] = d1.y; adv[6] = d1.z; adv[7] = d1.w;
        }
    }
    float ssp[8], sdp[8];
    #pragma unroll
    for (int i = 0; i < 8; i++) {
        float ss = 0.f, sd = 0.f;
        #pragma unroll
        for (int j = 0; j < CPT; j++) {
            ss += acc[i][j] * asv[j];
            sd += acc[i][j] * adv[j];
        }
        ssp[i] = ss; sdp[i] = sd;
    }
    #pragma unroll
    for (int i = 0; i < 8; i++) {
        ssp[i] += __shfl_xor_sync(0xffffffff, ssp[i], 1);
        sdp[i] += __shfl_xor_sync(0xffffffff, sdp[i], 1);
        ssp[i] += __shfl_xor_sync(0xffffffff, ssp[i], 2);
        sdp[i] += __shfl_xor_sync(0xffffffff, sdp[i], 2);
        if (OUT == 32) {
            ssp[i] += __shfl_xor_sync(0xffffffff, ssp[i], 4);
            sdp[i] += __shfl_xor_sync(0xffffffff, sdp[i], 4);
        }
    }
    float lmax = -3.0e38f;
    if (OUT == 128) {
        if ((cg & 3) == 0) {
            int h = cg >> 2;
            #pragma unroll
            for (int i = 0; i < 8; i++) {
                int row = row0 + ng * 8 + i;
                if (row < NN) {
                    g_alsrc[row * HH + h] = ssp[i];
                    g_aldst[row * HH + h] = sdp[i];
                    lmax = fmaxf(lmax, ssp[i]);
                }
            }
            atomicMaxF(&smax[h], lmax);
        }
    } else {
        if (cg == 0) {
            #pragma unroll
            for (int i = 0; i < 8; i++) {
                int row = row0 + ng * 8 + i;
                if (row < NN) {
                    g_alsrc[row] = ssp[i];
                    g_aldst[row] = sdp[i];
                    lmax = fmaxf(lmax, ssp[i]);
                }
            }
            atomicMaxF(&smax[0], lmax);
        }
    }
    __syncthreads();
    if (tid < NH) atomicMaxF(&g_gmax[gslot + tid], smax[tid]);
}

// ---------------- single-pass fused GAT aggregation (warp per dst, fp16 gather) --
__global__ __launch_bounds__(256) void gat_agg4_kernel(const float* __restrict__ b,
                                                       int gslot, int do_elu) {
    __shared__ int    ss[8][32];
    __shared__ float4 ww[8][32];

    int warp = (blockIdx.x * blockDim.x + threadIdx.x) >> 5;
    if (warp >= NN) return;
    int lane = threadIdx.x & 31;
    int wslot = (threadIdx.x >> 5) & 7;
    int d = warp;
    int start = g_rowptr[d], end = g_rowptr[d + 1];

    float4 ad = *(const float4*)&g_aldst[d * HH];
    float4 gm = *(const float4*)&g_gmax[gslot];
    float4 m;
    m.x = gm.x + ad.x; m.x = (m.x > 0.f) ? m.x : 0.2f * m.x;
    m.y = gm.y + ad.y; m.y = (m.y > 0.f) ? m.y : 0.2f * m.y;
    m.z = gm.z + ad.z; m.z = (m.z > 0.f) ? m.z : 0.2f * m.z;
    m.w = gm.w + ad.w; m.w = (m.w > 0.f) ? m.w : 0.2f * m.w;

    const int h0 = lane >> 4;
    const int h1 = 2 + h0;

    float4 denom = make_float4(0.f, 0.f, 0.f, 0.f);
    float a0x = 0.f, a0y = 0.f, a1x = 0.f, a1y = 0.f;

    for (int base = start; base < end; base += 32) {
        int i = base + lane;
        float4 w = make_float4(0.f, 0.f, 0.f, 0.f);
        int s = 0;
        if (i < end) {
            s = g_csrc[i];
            float4 v = *(const float4*)&g_alsrc[s * HH];
            v.x += ad.x; v.y += ad.y; v.z += ad.z; v.w += ad.w;
            v.x = (v.x > 0.f) ? v.x : 0.2f * v.x;
            v.y = (v.y > 0.f) ? v.y : 0.2f * v.y;
            v.z = (v.z > 0.f) ? v.z : 0.2f * v.z;
            v.w = (v.w > 0.f) ? v.w : 0.2f * v.w;
            w.x = __expf(v.x - m.x);
            w.y = __expf(v.y - m.y);
            w.z = __expf(v.z - m.z);
            w.w = __expf(v.w - m.w);
        }
        denom.x += w.x; denom.y += w.y; denom.z += w.z; denom.w += w.w;
        ss[wslot][lane] = s;
        ww[wslot][lane] = w;
        __syncwarp();
        int n = min(32, end - base);
        for (int j = 0; j < n; j++) {
            int sj = ss[wslot][j];
            const float* wjp = (const float*)&ww[wslot][j];
            float w0 = wjp[h0];
            float w1 = wjp[h1];
            const __half2* hp = (const __half2*)(g_lin16 + sj * HC);
            float2 m0 = __half22float2(hp[lane]);
            float2 m1 = __half22float2(hp[32 + lane]);
            a0x += w0 * m0.x; a0y += w0 * m0.y;
            a1x += w1 * m1.x; a1y += w1 * m1.y;
        }
        __syncwarp();
    }

    #pragma unroll
    for (int o = 16; o >= 1; o >>= 1) {
        denom.x += __shfl_xor_sync(0xffffffff, denom.x, o);
        denom.y += __shfl_xor_sync(0xffffffff, denom.y, o);
        denom.z += __shfl_xor_sync(0xffffffff, denom.z, o);
        denom.w += __shfl_xor_sync(0xffffffff, denom.w, o);
    }
    float rd0 = 1.f / ((h0 == 0 ? denom.x : denom.y) + 1e-16f);
    float rd1 = 1.f / ((h1 == 2 ? denom.z : denom.w) + 1e-16f);

    float2 b0 = *(const float2*)&b[2 * lane];
    float2 b1 = *(const float2*)&b[64 + 2 * lane];
    a0x = a0x * rd0 + b0.x;
    a0y = a0y * rd0 + b0.y;
    a1x = a1x * rd1 + b1.x;
    a1y = a1y * rd1 + b1.y;
    if (do_elu) {
        a0x = (a0x > 0.f) ? a0x : (__expf(a0x) - 1.f);
        a0y = (a0y > 0.f) ? a0y : (__expf(a0y) - 1.f);
        a1x = (a1x > 0.f) ? a1x : (__expf(a1x) - 1.f);
        a1y = (a1y > 0.f) ? a1y : (__expf(a1y) - 1.f);
    }
    float* o = g_act + d * HC;
    *(float2*)&o[2 * lane] = make_float2(a0x, a0y);
    *(float2*)&o[64 + 2 * lane] = make_float2(a1x, a1y);
}

// layer 3 (H=1) fused with classifier head + embedding write
__global__ __launch_bounds__(256) void gat_agg1_head_kernel(
        const float* __restrict__ b, const float* __restrict__ Wc,
        const float* __restrict__ bc, float* __restrict__ out) {
    __shared__ int   ss[8][32];
    __shared__ float ww[8][32];

    int warp = (blockIdx.x * blockDim.x + threadIdx.x) >> 5;
    if (warp >= NN) return;
    int lane = threadIdx.x & 31;
    int wslot = (threadIdx.x >> 5) & 7;
    int d = warp;
    int start = g_rowptr[d], end = g_rowptr[d + 1];

    float ad = g_aldst[d];
    float gm = g_gmax[8];
    float m = gm + ad; m = (m > 0.f) ? m : 0.2f * m;

    float denom = 0.f;
    float acc = 0.f;

    for (int base = start; base < end; base += 32) {
        int i = base + lane;
        float w = 0.f;
        int s = 0;
        if (i < end) {
            s = g_csrc[i];
            float v = g_alsrc[s] + ad;
            v = (v > 0.f) ? v : 0.2f * v;
            w = __expf(v - m);
        }
        denom += w;
        ss[wslot][lane] = s;
        ww[wslot][lane] = w;
        __syncwarp();
        int n = min(32, end - base);
        for (int j = 0; j < n; j++) {
            acc += ww[wslot][j] * __half2float(g_lin16[ss[wslot][j] * CC + lane]);
        }
        __syncwarp();
    }
    #pragma unroll
    for (int o = 16; o >= 1; o >>= 1)
        denom += __shfl_xor_sync(0xffffffff, denom, o);

    float h = acc / (denom + 1e-16f) + b[lane];

    out[NN * 2 + d * CC + lane] = h;

    float o0 = h * Wc[lane * 2 + 0];
    float o1 = h * Wc[lane * 2 + 1];
    #pragma unroll
    for (int o = 16; o >= 1; o >>= 1) {
        o0 += __shfl_xor_sync(0xffffffff, o0, o);
        o1 += __shfl_xor_sync(0xffffffff, o1, o);
    }
    if (lane == 0) {
        out[d * 2 + 0] = o0 + bc[0];
        out[d * 2 + 1] = o1 + bc[1];
    }
}

// ---------------- launch ----------------
extern "C" void kernel_launch(void* const* d_in, const int* in_sizes, int n_in,
                              void* d_out, int out_size) {
    const float* x   = (const float*)d_in[0];
    const int*   ei  = (const int*)d_in[1];
    const float* W1  = (const float*)d_in[2];
    const float* a1s = (const float*)d_in[3];
    const float* a1d = (const float*)d_in[4];
    const float* b1  = (const float*)d_in[5];
    const float* W2  = (const float*)d_in[6];
    const float* a2s = (const float*)d_in[7];
    const float* a2d = (const float*)d_in[8];
    const float* b2  = (const float*)d_in[9];
    const float* W3  = (const float*)d_in[10];
    const float* a3s = (const float*)d_in[11];
    const float* a3d = (const float*)d_in[12];
    const float* b3  = (const float*)d_in[13];
    const float* Wc  = (const float*)d_in[14];
    const float* bc  = (const float*)d_in[15];
    float* out = (float*)d_out;

    const int T = 256;
    const int gE = (ETOT + T - 1) / T;
    const int gN = (NN + T - 1) / T;
    const int gW = (NN * 32 + T - 1) / T;

    cudaStream_t s0 = 0;                // capture-origin stream
    cudaStream_t sA = g_sp.sA;          // CSR branch
    cudaStream_t sB = g_sp.sB;          // GEMM1 branch

    // shared prologue on the capture stream
    detect_kernel<<<1, 32, 0, s0>>>(ei);

    // fork
    cudaEventRecord(g_sp.evFork, s0);
    cudaStreamWaitEvent(sA, g_sp.evFork, 0);
    cudaStreamWaitEvent(sB, g_sp.evFork, 0);

    // ---- branch A: CSR build ----
    zero_fill_kernel<<<gN, T, 0, sA>>>();
    count_kernel<<<gE, T, 0, sA>>>(ei);
    block_sum_kernel<<<NBLK, 1024, 0, sA>>>();
    scan_bsum_kernel<<<1, 64, 0, sA>>>();
    rowptr_kernel<<<NBLK, 1024, 0, sA>>>();
    csr_fill_kernel<<<gE, T, 0, sA>>>(ei);
    cudaEventRecord(g_sp.evA, sA);

    // ---- branch B: layer-1 GEMM + attention logits ----
    gemm_al_kernel<128, false><<<(NN + 63) / 64, 128, 0, sB>>>(x, W1, a1s, a1d, 0);
    cudaEventRecord(g_sp.evB, sB);

    // join on the capture stream
    cudaStreamWaitEvent(s0, g_sp.evA, 0);
    cudaStreamWaitEvent(s0, g_sp.evB, 0);

    // ---- layer 1 aggregation ----
    gat_agg4_kernel<<<gW, T, 0, s0>>>(b1, 0, 1);

    // ---- layer 2 ----
    gemm_al_kernel<128, true><<<(NN + 63) / 64, 128, 0, s0>>>(nullptr, W2, a2s, a2d, 4);
    gat_agg4_kernel<<<gW, T, 0, s0>>>(b2, 4, 1);

    // ---- layer 3 (heads=1) + classifier head ----
    gemm_al_kernel<32, true><<<(NN + 127) / 128, 128, 0, s0>>>(nullptr, W3, a3s, a3d, 8);
    gat_agg1_head_kernel<<<gW, T, 0, s0>>>(b3, Wc, bc, out);
}